// round 3
// baseline (speedup 1.0000x reference)
#include <cuda_runtime.h>
#include <cuda_bf16.h>
#include <math.h>

// ---------------------------------------------------------------------------
// MPConv: out[n] = segment_sum_j( gelu(LN( [x[i]|x[j]|ea] @ W1 + b1 )) @ W2 + b2 )
//
// Factored: A = x @ W1[0:64], B = x @ W1[64:128]  (node precompute)
//           h = A[i] + B[j] + ea @ W1[128:160] + b1   (edge kernel)
// fp32 math via packed fma.rn.f32x2 (FFMA2), K-dimension packing.
// ---------------------------------------------------------------------------

#define MAXN 100000
#define CH   64
#define ED   32

__device__ float g_A[(size_t)MAXN * CH];
__device__ float g_B[(size_t)MAXN * CH];
__device__ int   g_idx64;   // 1 if edge_index stored as int64, 0 if int32

typedef unsigned long long u64;

__device__ __forceinline__ u64 pk2(float lo, float hi) {
    u64 r; asm("mov.b64 %0, {%1,%2};" : "=l"(r) : "f"(lo), "f"(hi)); return r;
}
__device__ __forceinline__ void unpk2(u64 v, float& lo, float& hi) {
    asm("mov.b64 {%0,%1}, %2;" : "=f"(lo), "=f"(hi) : "l"(v));
}
__device__ __forceinline__ u64 fma2(u64 a, u64 b, u64 c) {
    u64 d; asm("fma.rn.f32x2 %0, %1, %2, %3;" : "=l"(d) : "l"(a), "l"(b), "l"(c));
    return d;
}
__device__ __forceinline__ float hsum2(u64 v) {
    float a, b; unpk2(v, a, b); return a + b;
}

// ---------------------------------------------------------------------------
// Detect whether edge_index is int64 (odd 32-bit words all zero) or int32.
// Deterministic: recomputed every launch.
// ---------------------------------------------------------------------------
__global__ void detect_idx_kernel(const int* __restrict__ ei) {
    int t = threadIdx.x;
    int ok = 1;
    for (int q = t; q < 1024; q += blockDim.x) {
        if (ei[2 * q + 1] != 0) ok = 0;
    }
    ok = __syncthreads_and(ok);
    if (t == 0) g_idx64 = ok;
}

// ---------------------------------------------------------------------------
// Node precompute: A[n][c] = sum_k x[n][k] * W1[k][c]
//                  B[n][c] = sum_k x[n][k] * W1[64+k][c]
// 256 threads = 4 node groups x 64 channels. Weights in registers (packed).
// ---------------------------------------------------------------------------
__global__ __launch_bounds__(256) void node_pre_kernel(
    const float* __restrict__ x, const float* __restrict__ W1, int n_nodes)
{
    const int t = threadIdx.x;
    const int c = t & 63;
    const int grp = t >> 6;

    u64 wa[32], wb[32];
#pragma unroll
    for (int q = 0; q < 32; q++) {
        wa[q] = pk2(W1[(2 * q) * CH + c],      W1[(2 * q + 1) * CH + c]);
        wb[q] = pk2(W1[(64 + 2 * q) * CH + c], W1[(64 + 2 * q + 1) * CH + c]);
    }

    __shared__ float xs[4][CH];

    for (int n0 = blockIdx.x * 4; n0 < n_nodes; n0 += gridDim.x * 4) {
        const int node = n0 + grp;
        if (node < n_nodes) xs[grp][c] = x[(size_t)node * CH + c];
        __syncthreads();
        if (node < n_nodes) {
            const u64* xp = (const u64*)xs[grp];
            u64 aa = 0ull, bb = 0ull;   // (0.0f, 0.0f)
#pragma unroll
            for (int q = 0; q < 32; q++) {
                u64 xq = xp[q];
                aa = fma2(xq, wa[q], aa);
                bb = fma2(xq, wb[q], bb);
            }
            g_A[(size_t)node * CH + c] = hsum2(aa);
            g_B[(size_t)node * CH + c] = hsum2(bb);
        }
        __syncthreads();
    }
}

// ---------------------------------------------------------------------------
// Edge kernel: 256 threads = 4 edge groups x 64 channels (2 warps / edge).
// Weights (W1 edge-part column + W2 column) in registers; ea & gelu(h)
// broadcast via global/shared; LN via warp shuffle + 2-warp combine.
// ---------------------------------------------------------------------------
__global__ __launch_bounds__(256) void edge_kernel(
    const void* __restrict__ ei_raw,
    const float* __restrict__ ea,
    const float* __restrict__ W1, const float* __restrict__ b1,
    const float* __restrict__ gamma, const float* __restrict__ beta,
    const float* __restrict__ W2, const float* __restrict__ b2,
    float* __restrict__ out, int n_edges)
{
    const int t = threadIdx.x;
    const int c = t & 63;
    const int grp = t >> 6;
    const int flag64 = g_idx64;

    u64 w1e[16], w2p[32];
#pragma unroll
    for (int q = 0; q < 16; q++)
        w1e[q] = pk2(W1[(128 + 2 * q) * CH + c], W1[(128 + 2 * q + 1) * CH + c]);
#pragma unroll
    for (int q = 0; q < 32; q++)
        w2p[q] = pk2(W2[(2 * q) * CH + c], W2[(2 * q + 1) * CH + c]);

    const float b1c = b1[c], gmc = gamma[c], btc = beta[c], b2c = b2[c];

    __shared__ float  gsh[4][CH];
    __shared__ float2 sred[4][2];

    const long long* ei64 = (const long long*)ei_raw;
    const int*       ei32 = (const int*)ei_raw;

    for (int e0 = blockIdx.x * 4; e0 < n_edges; e0 += gridDim.x * 4) {
        const int e = e0 + grp;
        const bool act = (e < n_edges);

        int j = 0;
        float h = 0.0f;
        if (act) {
            int i;
            if (flag64) { i = (int)ei64[e]; j = (int)ei64[(size_t)n_edges + e]; }
            else        { i = ei32[e];      j = ei32[(size_t)n_edges + e]; }
            const float Av = g_A[(size_t)i * CH + c];
            const float Bv = g_B[(size_t)j * CH + c];
            const u64* eap = (const u64*)(ea + (size_t)e * ED);
            u64 acc = 0ull;
#pragma unroll
            for (int q = 0; q < 16; q++) acc = fma2(eap[q], w1e[q], acc);
            h = b1c + Av + Bv + hsum2(acc);
        }

        // LayerNorm stats: warp reduce (32 ch per warp) + 2-warp combine.
        float s = h, s2 = h * h;
#pragma unroll
        for (int o = 16; o; o >>= 1) {
            s  += __shfl_xor_sync(0xffffffffu, s,  o);
            s2 += __shfl_xor_sync(0xffffffffu, s2, o);
        }
        if ((t & 31) == 0) sred[grp][(t >> 5) & 1] = make_float2(s, s2);
        __syncthreads();

        float gval = 0.0f;
        if (act) {
            const float2 p0 = sred[grp][0];
            const float2 p1 = sred[grp][1];
            const float mean = (p0.x + p1.x) * (1.0f / 64.0f);
            const float m2   = (p0.y + p1.y) * (1.0f / 64.0f);
            const float var  = m2 - mean * mean;
            const float rstd = rsqrtf(var + 1e-5f);
            const float hn   = (h - mean) * rstd * gmc + btc;
            // exact GELU: 0.5*x*(1+erf(x/sqrt(2)))
            gval = 0.5f * hn * (1.0f + erff(hn * 0.70710678118654752440f));
        }
        gsh[grp][c] = gval;
        __syncthreads();

        if (act) {
            const u64* gp = (const u64*)gsh[grp];
            u64 acc = 0ull;
#pragma unroll
            for (int q = 0; q < 32; q++) acc = fma2(gp[q], w2p[q], acc);
            const float m = hsum2(acc) + b2c;
            atomicAdd(&out[(size_t)j * CH + c], m);
        }
        __syncthreads();
    }
}

// ---------------------------------------------------------------------------
// Inputs (metadata order): x[N,64] f32, edge_index[2,E] (int32 or int64),
// edge_attr[E,32] f32, W1[160,64], b1[64], gamma[64], beta[64],
// W2[64,64], b2[64]. Output: [N,64] f32.
// ---------------------------------------------------------------------------
extern "C" void kernel_launch(void* const* d_in, const int* in_sizes, int n_in,
                              void* d_out, int out_size)
{
    const float* x     = (const float*)d_in[0];
    const void*  ei    = d_in[1];
    const float* ea    = (const float*)d_in[2];
    const float* W1    = (const float*)d_in[3];
    const float* b1    = (const float*)d_in[4];
    const float* gamma = (const float*)d_in[5];
    const float* beta  = (const float*)d_in[6];
    const float* W2    = (const float*)d_in[7];
    const float* b2    = (const float*)d_in[8];
    float* out = (float*)d_out;

    const int n_nodes = in_sizes[0] / CH;
    const int n_edges = in_sizes[2] / ED;   // from edge_attr (dtype-unambiguous)
    if (n_nodes > MAXN) return;

    cudaMemsetAsync(d_out, 0, (size_t)out_size * sizeof(float));

    detect_idx_kernel<<<1, 256>>>((const int*)ei);

    int npre_blocks = (n_nodes + 3) / 4;
    if (npre_blocks > 1024) npre_blocks = 1024;
    node_pre_kernel<<<npre_blocks, 256>>>(x, W1, n_nodes);

    int nedge_blocks = (n_edges + 3) / 4;
    if (nedge_blocks > 1024) nedge_blocks = 1024;
    edge_kernel<<<nedge_blocks, 256>>>(ei, ea, W1, b1, gamma, beta, W2, b2,
                                       out, n_edges);
}

// round 4
// speedup vs baseline: 1.5753x; 1.5753x over previous
#include <cuda_runtime.h>
#include <cuda_bf16.h>
#include <math.h>

// ---------------------------------------------------------------------------
// MPConv: out[n] = segment_sum_j( gelu(LN( [x[i]|x[j]|ea] @ W1 + b1 )) @ W2 + b2 )
// Factored: A = x@W1[0:64], B = x@W1[64:128] per node; per edge only
//           h = A[i] + B[j] + ea@W1[128:160] + b1.
// fp32 via packed fma.rn.f32x2, K-dim packing, weights in registers.
// v3: 128-thr blocks (3/SM), software-pipelined gathers + ea smem staging,
//     dual accumulators, packed LN reduce, red.global.add.v4.f32 scatter.
// ---------------------------------------------------------------------------

#define MAXN 100000
#define CH   64
#define ED   32

__device__ float g_A[(size_t)MAXN * CH];
__device__ float g_B[(size_t)MAXN * CH];
__device__ int   g_idx64;

typedef unsigned long long u64;

__device__ __forceinline__ u64 pk2(float lo, float hi) {
    u64 r; asm("mov.b64 %0, {%1,%2};" : "=l"(r) : "f"(lo), "f"(hi)); return r;
}
__device__ __forceinline__ void unpk2(u64 v, float& lo, float& hi) {
    asm("mov.b64 {%0,%1}, %2;" : "=f"(lo), "=f"(hi) : "l"(v));
}
__device__ __forceinline__ u64 fma2(u64 a, u64 b, u64 c) {
    u64 d; asm("fma.rn.f32x2 %0, %1, %2, %3;" : "=l"(d) : "l"(a), "l"(b), "l"(c));
    return d;
}
__device__ __forceinline__ u64 add2(u64 a, u64 b) {
    u64 d; asm("add.rn.f32x2 %0, %1, %2;" : "=l"(d) : "l"(a), "l"(b));
    return d;
}
__device__ __forceinline__ float hsum2(u64 v) {
    float a, b; unpk2(v, a, b); return a + b;
}
__device__ __forceinline__ void red4(float* p, float4 v) {
    asm volatile("red.global.add.v4.f32 [%0], {%1,%2,%3,%4};"
                 :: "l"(p), "f"(v.x), "f"(v.y), "f"(v.z), "f"(v.w) : "memory");
}

// ---------------------------------------------------------------------------
__global__ void detect_idx_kernel(const int* __restrict__ ei) {
    int t = threadIdx.x;
    int ok = 1;
    for (int q = t; q < 1024; q += blockDim.x)
        if (ei[2 * q + 1] != 0) ok = 0;
    ok = __syncthreads_and(ok);
    if (t == 0) g_idx64 = ok;
}

// ---------------------------------------------------------------------------
// Node precompute: A[n][c], B[n][c]. 256 thr = 4 nodes x 64 ch.
// ---------------------------------------------------------------------------
__global__ __launch_bounds__(256) void node_pre_kernel(
    const float* __restrict__ x, const float* __restrict__ W1, int n_nodes)
{
    const int t = threadIdx.x;
    const int c = t & 63;
    const int grp = t >> 6;

    u64 wa[32], wb[32];
#pragma unroll
    for (int q = 0; q < 32; q++) {
        wa[q] = pk2(W1[(2 * q) * CH + c],      W1[(2 * q + 1) * CH + c]);
        wb[q] = pk2(W1[(64 + 2 * q) * CH + c], W1[(64 + 2 * q + 1) * CH + c]);
    }

    __shared__ float xs[4][CH];

    for (int n0 = blockIdx.x * 4; n0 < n_nodes; n0 += gridDim.x * 4) {
        const int node = n0 + grp;
        if (node < n_nodes) xs[grp][c] = x[(size_t)node * CH + c];
        __syncthreads();
        if (node < n_nodes) {
            const ulonglong2* xp = (const ulonglong2*)xs[grp];
            u64 a0 = 0ull, a1 = 0ull, b0 = 0ull, b1 = 0ull;
#pragma unroll
            for (int q = 0; q < 16; q++) {
                ulonglong2 xv = xp[q];
                a0 = fma2(xv.x, wa[2 * q],     a0);
                a1 = fma2(xv.y, wa[2 * q + 1], a1);
                b0 = fma2(xv.x, wb[2 * q],     b0);
                b1 = fma2(xv.y, wb[2 * q + 1], b1);
            }
            g_A[(size_t)node * CH + c] = hsum2(add2(a0, a1));
            g_B[(size_t)node * CH + c] = hsum2(add2(b0, b1));
        }
        __syncthreads();
    }
}

// ---------------------------------------------------------------------------
// Edge kernel v3. 128 threads = 2 edge slots x 64 channels.
// ---------------------------------------------------------------------------
__global__ void __launch_bounds__(128, 3) edge_kernel(
    const void* __restrict__ ei_raw,
    const float* __restrict__ ea,
    const float* __restrict__ W1, const float* __restrict__ b1,
    const float* __restrict__ gamma, const float* __restrict__ beta,
    const float* __restrict__ W2, const float* __restrict__ b2,
    float* __restrict__ out, int n_edges)
{
    const int t    = threadIdx.x;
    const int c    = t & 63;
    const int slot = t >> 6;
    const int hw   = (t >> 5) & 1;     // warp-half within slot
    const int lead = (t & 63);         // 0..63 within slot
    const int flag64 = g_idx64;

    u64 w1e[16], w2p[32];
#pragma unroll
    for (int q = 0; q < 16; q++)
        w1e[q] = pk2(W1[(128 + 2 * q) * CH + c], W1[(128 + 2 * q + 1) * CH + c]);
#pragma unroll
    for (int q = 0; q < 32; q++)
        w2p[q] = pk2(W2[(2 * q) * CH + c], W2[(2 * q + 1) * CH + c]);

    const float b1c = b1[c], gmc = gamma[c], btc = beta[c], b2c = b2[c];

    __shared__ float  ea_s[2][2][ED];   // [slot][buf][k]
    __shared__ float2 sred[2][2];
    __shared__ float  gsh[2][CH];
    __shared__ float  msh[2][CH];

    const long long* ei64 = (const long long*)ei_raw;
    const int*       ei32 = (const int*)ei_raw;
    const int estep = gridDim.x * 2;

    auto load_idx = [&](int ee, int& ii, int& jj) {
        if (flag64) { ii = (int)ei64[ee]; jj = (int)ei64[(size_t)n_edges + ee]; }
        else        { ii = ei32[ee];      jj = ei32[(size_t)n_edges + ee]; }
    };

    // ---- prologue: edge(0) fully loaded, edge(1) indices loaded ----
    int e = blockIdx.x * 2 + slot;
    int ec = (e < n_edges) ? e : 0;
    int i0, j0; load_idx(ec, i0, j0);
    float Af = g_A[(size_t)i0 * CH + c];
    float Bf = g_B[(size_t)j0 * CH + c];
    if (lead < 8)
        ((float4*)ea_s[slot][0])[lead] = ((const float4*)(ea + (size_t)ec * ED))[lead];
    int e1 = e + estep;
    int e1c = (e1 < n_edges) ? e1 : 0;
    int i1, j1; load_idx(e1c, i1, j1);
    __syncthreads();

    int buf = 0;
    for (int e0 = blockIdx.x * 2; e0 < n_edges; e0 += estep) {
        e = e0 + slot;
        const bool act = (e < n_edges);

        // -------- phase 1: h = b1 + A[i] + B[j] + ea @ W1e --------
        float h = 0.0f;
        {
            const ulonglong2* ep = (const ulonglong2*)ea_s[slot][buf];
            u64 a0 = 0ull, a1 = 0ull;
#pragma unroll
            for (int q = 0; q < 8; q++) {
                ulonglong2 v = ep[q];
                a0 = fma2(v.x, w1e[2 * q],     a0);
                a1 = fma2(v.y, w1e[2 * q + 1], a1);
            }
            h = b1c + Af + Bf + hsum2(add2(a0, a1));
        }

        // -------- prefetch for iteration t+1 / t+2 --------
        float Anx = g_A[(size_t)i1 * CH + c];
        float Bnx = g_B[(size_t)j1 * CH + c];
        float4 ea_nx = make_float4(0.f, 0.f, 0.f, 0.f);
        {
            int en  = e0 + estep + slot;
            int enc = (en < n_edges) ? en : 0;
            if (lead < 8)
                ea_nx = ((const float4*)(ea + (size_t)enc * ED))[lead];
        }
        int e2  = e0 + 2 * estep + slot;
        int e2c = (e2 < n_edges) ? e2 : 0;
        int i2, j2; load_idx(e2c, i2, j2);

        // -------- LayerNorm stats: packed (s, s2) butterfly --------
        u64 ss = pk2(h, h * h);
#pragma unroll
        for (int o = 16; o; o >>= 1)
            ss = add2(ss, __shfl_xor_sync(0xffffffffu, ss, o));
        if ((t & 31) == 0) {
            float a, b; unpk2(ss, a, b);
            sred[slot][hw] = make_float2(a, b);
        }
        __syncthreads();                                   // sync1

        // write next ea buffer (safe: between sync1 and sync2)
        if (lead < 8) ((float4*)ea_s[slot][buf ^ 1])[lead] = ea_nx;

        // -------- phase 2: LN + GELU --------
        {
            const float2 p0 = sred[slot][0];
            const float2 p1 = sred[slot][1];
            const float mean = (p0.x + p1.x) * (1.0f / 64.0f);
            const float m2   = (p0.y + p1.y) * (1.0f / 64.0f);
            const float var  = m2 - mean * mean;
            const float rstd = rsqrtf(var + 1e-5f);
            const float hn   = (h - mean) * rstd * gmc + btc;
            const float gv   = 0.5f * hn * (1.0f + erff(hn * 0.70710678118654752440f));
            gsh[slot][c] = act ? gv : 0.0f;
        }
        __syncthreads();                                   // sync2

        // -------- phase 3: m = g @ W2 + b2 --------
        {
            const ulonglong2* gp = (const ulonglong2*)gsh[slot];
            u64 a0 = 0ull, a1 = 0ull;
#pragma unroll
            for (int q = 0; q < 16; q++) {
                ulonglong2 v = gp[q];
                a0 = fma2(v.x, w2p[2 * q],     a0);
                a1 = fma2(v.y, w2p[2 * q + 1], a1);
            }
            msh[slot][c] = hsum2(add2(a0, a1)) + b2c;
        }
        const int jcur = j0;
        __syncthreads();                                   // sync3

        // -------- phase 4: vector scatter-add --------
        if (act && lead < 16) {
            float4 mv = ((const float4*)msh[slot])[lead];
            red4(out + (size_t)jcur * CH + 4 * lead, mv);
        }

        // rotate pipeline registers
        Af = Anx; Bf = Bnx;
        i0 = i1; j0 = j1;
        i1 = i2; j1 = j2;
        buf ^= 1;
    }
}

// ---------------------------------------------------------------------------
// Inputs: x[N,64] f32, edge_index[2,E] (i32/i64), edge_attr[E,32] f32,
// W1[160,64], b1[64], gamma[64], beta[64], W2[64,64], b2[64]. Out [N,64] f32.
// ---------------------------------------------------------------------------
extern "C" void kernel_launch(void* const* d_in, const int* in_sizes, int n_in,
                              void* d_out, int out_size)
{
    const float* x     = (const float*)d_in[0];
    const void*  ei    = d_in[1];
    const float* ea    = (const float*)d_in[2];
    const float* W1    = (const float*)d_in[3];
    const float* b1    = (const float*)d_in[4];
    const float* gamma = (const float*)d_in[5];
    const float* beta  = (const float*)d_in[6];
    const float* W2    = (const float*)d_in[7];
    const float* b2    = (const float*)d_in[8];
    float* out = (float*)d_out;

    const int n_nodes = in_sizes[0] / CH;
    const int n_edges = in_sizes[2] / ED;
    if (n_nodes > MAXN) return;

    cudaMemsetAsync(d_out, 0, (size_t)out_size * sizeof(float));

    detect_idx_kernel<<<1, 256>>>((const int*)ei);

    int npre_blocks = (n_nodes + 3) / 4;
    if (npre_blocks > 1024) npre_blocks = 1024;
    node_pre_kernel<<<npre_blocks, 256>>>(x, W1, n_nodes);

    edge_kernel<<<1776, 128>>>(ei, ea, W1, b1, gamma, beta, W2, b2,
                               out, n_edges);
}

// round 6
// speedup vs baseline: 2.3304x; 1.4793x over previous
#include <cuda_runtime.h>
#include <cuda_bf16.h>
#include <math.h>

// ---------------------------------------------------------------------------
// MPConv: out[n] = segment_sum_j( gelu(LN( [x[i]|x[j]|ea] @ W1 + b1 )) @ W2 + b2 )
// Factored: A = x@W1[0:64], B = x@W1[64:128]+b1 per node; per edge:
//           h = A[i] + B[j] + ea@W1[128:160].
// v4: UNROLL=3 edges/slot/iter (6/block), cp.async triple-buffered ea,
//     2-ahead idx / 1-ahead A,B prefetch, fma.rn.f32x2 everywhere.
// ---------------------------------------------------------------------------

#define MAXN 100000
#define CH   64
#define ED   32
#define UN   3

__device__ float g_A[(size_t)MAXN * CH];
__device__ float g_B[(size_t)MAXN * CH];
__device__ int   g_idx64;

typedef unsigned long long u64;

__device__ __forceinline__ u64 pk2(float lo, float hi) {
    u64 r; asm("mov.b64 %0, {%1,%2};" : "=l"(r) : "f"(lo), "f"(hi)); return r;
}
__device__ __forceinline__ void unpk2(u64 v, float& lo, float& hi) {
    asm("mov.b64 {%0,%1}, %2;" : "=f"(lo), "=f"(hi) : "l"(v));
}
__device__ __forceinline__ u64 fma2(u64 a, u64 b, u64 c) {
    u64 d; asm("fma.rn.f32x2 %0, %1, %2, %3;" : "=l"(d) : "l"(a), "l"(b), "l"(c));
    return d;
}
__device__ __forceinline__ u64 add2(u64 a, u64 b) {
    u64 d; asm("add.rn.f32x2 %0, %1, %2;" : "=l"(d) : "l"(a), "l"(b));
    return d;
}
__device__ __forceinline__ float hsum2(u64 v) {
    float a, b; unpk2(v, a, b); return a + b;
}
__device__ __forceinline__ void red4(float* p, float4 v) {
    asm volatile("red.global.add.v4.f32 [%0], {%1,%2,%3,%4};"
                 :: "l"(p), "f"(v.x), "f"(v.y), "f"(v.z), "f"(v.w) : "memory");
}
__device__ __forceinline__ void cpasync16(void* smem_dst, const void* gmem_src) {
    unsigned sa = (unsigned)__cvta_generic_to_shared(smem_dst);
    asm volatile("cp.async.cg.shared.global [%0], [%1], 16;"
                 :: "r"(sa), "l"(gmem_src) : "memory");
}
__device__ __forceinline__ void cpasync_commit() {
    asm volatile("cp.async.commit_group;" ::: "memory");
}
__device__ __forceinline__ void cpasync_wait1() {
    asm volatile("cp.async.wait_group 1;" ::: "memory");
}

// ---------------------------------------------------------------------------
// Node precompute (+ idx-width detection in block 0):
//   A[n][c] = x[n] . W1[0:64, c]        B[n][c] = x[n] . W1[64:128, c] + b1[c]
// ---------------------------------------------------------------------------
__global__ __launch_bounds__(256) void node_pre_kernel(
    const float* __restrict__ x, const float* __restrict__ W1,
    const float* __restrict__ b1, const int* __restrict__ ei, int n_nodes)
{
    const int t = threadIdx.x;
    const int c = t & 63;
    const int grp = t >> 6;

    if (blockIdx.x == 0) {           // fold detection here (one less launch)
        int ok = 1;
        for (int q = t; q < 1024; q += blockDim.x)
            if (ei[2 * q + 1] != 0) ok = 0;
        ok = __syncthreads_and(ok);
        if (t == 0) g_idx64 = ok;
    }

    u64 wa[32], wb[32];
#pragma unroll
    for (int q = 0; q < 32; q++) {
        wa[q] = pk2(W1[(2 * q) * CH + c],      W1[(2 * q + 1) * CH + c]);
        wb[q] = pk2(W1[(64 + 2 * q) * CH + c], W1[(64 + 2 * q + 1) * CH + c]);
    }
    const float b1c = b1[c];

    __shared__ __align__(16) float xs[4][CH];

    for (int n0 = blockIdx.x * 4; n0 < n_nodes; n0 += gridDim.x * 4) {
        const int node = n0 + grp;
        if (node < n_nodes) xs[grp][c] = x[(size_t)node * CH + c];
        __syncthreads();
        if (node < n_nodes) {
            const ulonglong2* xp = (const ulonglong2*)xs[grp];
            u64 a0 = 0ull, a1 = 0ull, b0 = 0ull, bacc1 = 0ull;
#pragma unroll
            for (int q = 0; q < 16; q++) {
                ulonglong2 xv = xp[q];
                a0    = fma2(xv.x, wa[2 * q],     a0);
                a1    = fma2(xv.y, wa[2 * q + 1], a1);
                b0    = fma2(xv.x, wb[2 * q],     b0);
                bacc1 = fma2(xv.y, wb[2 * q + 1], bacc1);
            }
            g_A[(size_t)node * CH + c] = hsum2(add2(a0, a1));
            g_B[(size_t)node * CH + c] = hsum2(add2(b0, bacc1)) + b1c;
        }
        __syncthreads();
    }
}

// ---------------------------------------------------------------------------
// Edge kernel v4: 128 threads = 2 slots x 64 ch; UN=3 edges per slot per iter.
// ---------------------------------------------------------------------------
__global__ void __launch_bounds__(128, 3) edge_kernel(
    const void* __restrict__ ei_raw,
    const float* __restrict__ ea,
    const float* __restrict__ W1,
    const float* __restrict__ gamma, const float* __restrict__ beta,
    const float* __restrict__ W2, const float* __restrict__ b2,
    float* __restrict__ out, int n_edges)
{
    const int t    = threadIdx.x;
    const int c    = t & 63;
    const int slot = t >> 6;
    const int hw   = (t >> 5) & 1;
    const int lead = t & 63;
    const int flag64 = g_idx64;

    u64 w1e[16], w2p[32];
#pragma unroll
    for (int q = 0; q < 16; q++)
        w1e[q] = pk2(W1[(128 + 2 * q) * CH + c], W1[(128 + 2 * q + 1) * CH + c]);
#pragma unroll
    for (int q = 0; q < 32; q++)
        w2p[q] = pk2(W2[(2 * q) * CH + c], W2[(2 * q + 1) * CH + c]);

    const float gmc = gamma[c], btc = beta[c], b2c = b2[c];

    __shared__ __align__(16) float ea_s[2][3][UN][ED];   // [slot][buf][u][k]
    __shared__ float2 sred[2][UN][2];
    __shared__ __align__(16) float gsh[2][UN][CH];
    __shared__ __align__(16) float msh[2][UN][CH];

    const long long* ei64 = (const long long*)ei_raw;
    const int*       ei32 = (const int*)ei_raw;
    const int estep = gridDim.x * 2 * UN;

    auto load_idx = [&](int ee, int& ii, int& jj) {
        if (flag64) { ii = (int)ei64[ee]; jj = (int)ei64[(size_t)n_edges + ee]; }
        else        { ii = ei32[ee];      jj = ei32[(size_t)n_edges + ee]; }
    };
    auto clampe = [&](int ee) { return (ee < n_edges) ? ee : 0; };

    // cp.async helper: stage ea rows of edges (ebase..ebase+UN) into buffer b.
    // 24 lead threads: u = lead>>3 (edge), v = lead&7 (16B chunk).
    auto stage_ea = [&](int ebase, int b) {
        if (lead < 8 * UN) {
            int u  = lead >> 3, v = lead & 7;
            int ee = clampe(ebase + u);
            cpasync16(&ea_s[slot][b][u][v * 4], ea + (size_t)ee * ED + v * 4);
        }
        cpasync_commit();
    };

    const int myoff = slot * UN;
    int e0 = blockIdx.x * 2 * UN;

    // ---------------- prologue ----------------
    int jc[UN];                      // current edges' scatter targets
    float Af[UN], Bf[UN];
    int i1[UN], j1[UN];              // iter+1 indices
    int i2[UN], j2[UN];              // iter+2 indices
#pragma unroll
    for (int u = 0; u < UN; u++) {
        int icur;
        load_idx(clampe(e0 + myoff + u), icur, jc[u]);
        Af[u] = g_A[(size_t)icur * CH + c];
        Bf[u] = g_B[(size_t)jc[u] * CH + c];
        load_idx(clampe(e0 + estep + myoff + u),     i1[u], j1[u]);
        load_idx(clampe(e0 + 2 * estep + myoff + u), i2[u], j2[u]);
    }
    stage_ea(e0 + myoff, 0);                 // iter 0
    stage_ea(e0 + estep + myoff, 1);         // iter 1
    cpasync_wait1();                         // iter-0 buffer complete
    __syncthreads();

    int buf = 0;
    for (; e0 < n_edges; e0 += estep) {
        // prefetch ea for iter+2 into third buffer
        stage_ea(e0 + 2 * estep + myoff, (buf + 2) % 3);

        // -------- phase 1: h[u] = A + B + ea.W1e (3 independent chains) ----
        float h[UN];
#pragma unroll
        for (int u = 0; u < UN; u++) {
            const ulonglong2* ep = (const ulonglong2*)ea_s[slot][buf][u];
            u64 a0 = 0ull, a1 = 0ull;
#pragma unroll
            for (int q = 0; q < 8; q++) {
                ulonglong2 v = ep[q];
                a0 = fma2(v.x, w1e[2 * q],     a0);
                a1 = fma2(v.y, w1e[2 * q + 1], a1);
            }
            h[u] = Af[u] + Bf[u] + hsum2(add2(a0, a1));
        }

        // -------- prefetch A/B for iter+1 (indices arrived 2 iters ago) ----
        float Anx[UN], Bnx[UN];
#pragma unroll
        for (int u = 0; u < UN; u++) {
            Anx[u] = g_A[(size_t)i1[u] * CH + c];
            Bnx[u] = g_B[(size_t)j1[u] * CH + c];
        }

        // -------- LN stats: packed (s, s2), 3 interleaved butterflies ------
        u64 ss[UN];
#pragma unroll
        for (int u = 0; u < UN; u++) ss[u] = pk2(h[u], h[u] * h[u]);
#pragma unroll
        for (int o = 16; o; o >>= 1) {
#pragma unroll
            for (int u = 0; u < UN; u++)
                ss[u] = add2(ss[u], __shfl_xor_sync(0xffffffffu, ss[u], o));
        }
        if ((t & 31) == 0) {
#pragma unroll
            for (int u = 0; u < UN; u++) {
                float a, b; unpk2(ss[u], a, b);
                sred[slot][u][hw] = make_float2(a, b);
            }
        }
        __syncthreads();                                   // sync1

        // -------- phase 2: LN + exact GELU (3 independent) -----------------
#pragma unroll
        for (int u = 0; u < UN; u++) {
            const float2 p0 = sred[slot][u][0];
            const float2 p1 = sred[slot][u][1];
            const float mean = (p0.x + p1.x) * (1.0f / 64.0f);
            const float m2   = (p0.y + p1.y) * (1.0f / 64.0f);
            const float rstd = rsqrtf(m2 - mean * mean + 1e-5f);
            const float hn   = (h[u] - mean) * rstd * gmc + btc;
            gsh[slot][u][c]  = 0.5f * hn *
                               (1.0f + erff(hn * 0.70710678118654752440f));
        }
        __syncthreads();                                   // sync2

        // -------- phase 3: m[u] = g.W2 + b2 (3 chains interleaved) ---------
#pragma unroll
        for (int u = 0; u < UN; u++) {
            const ulonglong2* gp = (const ulonglong2*)gsh[slot][u];
            u64 a0 = 0ull, a1 = 0ull;
#pragma unroll
            for (int q = 0; q < 16; q++) {
                ulonglong2 v = gp[q];
                a0 = fma2(v.x, w2p[2 * q],     a0);
                a1 = fma2(v.y, w2p[2 * q + 1], a1);
            }
            msh[slot][u][c] = hsum2(add2(a0, a1)) + b2c;
        }
        cpasync_wait1();            // iter+1 ea buffer complete before sync3
        __syncthreads();                                   // sync3

        // -------- phase 4: vector scatter-add ------------------------------
        if (lead < 16) {
#pragma unroll
            for (int u = 0; u < UN; u++) {
                if (e0 + myoff + u < n_edges) {
                    float4 mv = ((const float4*)msh[slot][u])[lead];
                    red4(out + (size_t)jc[u] * CH + 4 * lead, mv);
                }
            }
        }

        // -------- rotate pipeline ------------------------------------------
#pragma unroll
        for (int u = 0; u < UN; u++) {
            Af[u] = Anx[u]; Bf[u] = Bnx[u];
            jc[u] = j1[u];
            i1[u] = i2[u];  j1[u] = j2[u];
            load_idx(clampe(e0 + 3 * estep + myoff + u), i2[u], j2[u]);
        }
        buf = (buf + 1) % 3;
    }
}

// ---------------------------------------------------------------------------
// Inputs: x[N,64] f32, edge_index[2,E] (i32/i64), edge_attr[E,32] f32,
// W1[160,64], b1[64], gamma[64], beta[64], W2[64,64], b2[64]. Out [N,64] f32.
// ---------------------------------------------------------------------------
extern "C" void kernel_launch(void* const* d_in, const int* in_sizes, int n_in,
                              void* d_out, int out_size)
{
    const float* x     = (const float*)d_in[0];
    const void*  ei    = d_in[1];
    const float* ea    = (const float*)d_in[2];
    const float* W1    = (const float*)d_in[3];
    const float* b1    = (const float*)d_in[4];
    const float* gamma = (const float*)d_in[5];
    const float* beta  = (const float*)d_in[6];
    const float* W2    = (const float*)d_in[7];
    const float* b2    = (const float*)d_in[8];
    float* out = (float*)d_out;

    const int n_nodes = in_sizes[0] / CH;
    const int n_edges = in_sizes[2] / ED;
    if (n_nodes > MAXN) return;

    cudaMemsetAsync(d_out, 0, (size_t)out_size * sizeof(float));

    int npre_blocks = (n_nodes + 3) / 4;
    if (npre_blocks > 1024) npre_blocks = 1024;
    node_pre_kernel<<<npre_blocks, 256>>>(x, W1, b1, (const int*)ei, n_nodes);

    edge_kernel<<<1332, 128>>>(ei, ea, W1, gamma, beta, W2, b2, out, n_edges);
}

// round 7
// speedup vs baseline: 2.3427x; 1.0053x over previous
#include <cuda_runtime.h>
#include <cuda_bf16.h>
#include <math.h>

// ---------------------------------------------------------------------------
// MPConv: out[n] = segment_sum_j( gelu(LN( [x[i]|x[j]|ea] @ W1 + b1 )) @ W2 + b2 )
// Factored: A = x@W1[0:64], B = x@W1[64:128]+b1 per node; per edge:
//           h = A[i] + B[j] + ea@W1[128:160].
// v4: UNROLL=3 edges/slot/iter (6/block), cp.async triple-buffered ea,
//     2-ahead idx / 1-ahead A,B prefetch, fma.rn.f32x2 everywhere.
// ---------------------------------------------------------------------------

#define MAXN 100000
#define CH   64
#define ED   32
#define UN   3

__device__ float g_A[(size_t)MAXN * CH];
__device__ float g_B[(size_t)MAXN * CH];
__device__ int   g_idx64;

typedef unsigned long long u64;

__device__ __forceinline__ u64 pk2(float lo, float hi) {
    u64 r; asm("mov.b64 %0, {%1,%2};" : "=l"(r) : "f"(lo), "f"(hi)); return r;
}
__device__ __forceinline__ void unpk2(u64 v, float& lo, float& hi) {
    asm("mov.b64 {%0,%1}, %2;" : "=f"(lo), "=f"(hi) : "l"(v));
}
__device__ __forceinline__ u64 fma2(u64 a, u64 b, u64 c) {
    u64 d; asm("fma.rn.f32x2 %0, %1, %2, %3;" : "=l"(d) : "l"(a), "l"(b), "l"(c));
    return d;
}
__device__ __forceinline__ u64 add2(u64 a, u64 b) {
    u64 d; asm("add.rn.f32x2 %0, %1, %2;" : "=l"(d) : "l"(a), "l"(b));
    return d;
}
__device__ __forceinline__ float hsum2(u64 v) {
    float a, b; unpk2(v, a, b); return a + b;
}
__device__ __forceinline__ void red4(float* p, float4 v) {
    asm volatile("red.global.add.v4.f32 [%0], {%1,%2,%3,%4};"
                 :: "l"(p), "f"(v.x), "f"(v.y), "f"(v.z), "f"(v.w) : "memory");
}
__device__ __forceinline__ void cpasync16(void* smem_dst, const void* gmem_src) {
    unsigned sa = (unsigned)__cvta_generic_to_shared(smem_dst);
    asm volatile("cp.async.cg.shared.global [%0], [%1], 16;"
                 :: "r"(sa), "l"(gmem_src) : "memory");
}
__device__ __forceinline__ void cpasync_commit() {
    asm volatile("cp.async.commit_group;" ::: "memory");
}
__device__ __forceinline__ void cpasync_wait1() {
    asm volatile("cp.async.wait_group 1;" ::: "memory");
}

// ---------------------------------------------------------------------------
// Node precompute (+ idx-width detection in block 0):
//   A[n][c] = x[n] . W1[0:64, c]        B[n][c] = x[n] . W1[64:128, c] + b1[c]
// ---------------------------------------------------------------------------
__global__ __launch_bounds__(256) void node_pre_kernel(
    const float* __restrict__ x, const float* __restrict__ W1,
    const float* __restrict__ b1, const int* __restrict__ ei, int n_nodes)
{
    const int t = threadIdx.x;
    const int c = t & 63;
    const int grp = t >> 6;

    if (blockIdx.x == 0) {           // fold detection here (one less launch)
        int ok = 1;
        for (int q = t; q < 1024; q += blockDim.x)
            if (ei[2 * q + 1] != 0) ok = 0;
        ok = __syncthreads_and(ok);
        if (t == 0) g_idx64 = ok;
    }

    u64 wa[32], wb[32];
#pragma unroll
    for (int q = 0; q < 32; q++) {
        wa[q] = pk2(W1[(2 * q) * CH + c],      W1[(2 * q + 1) * CH + c]);
        wb[q] = pk2(W1[(64 + 2 * q) * CH + c], W1[(64 + 2 * q + 1) * CH + c]);
    }
    const float b1c = b1[c];

    __shared__ __align__(16) float xs[4][CH];

    for (int n0 = blockIdx.x * 4; n0 < n_nodes; n0 += gridDim.x * 4) {
        const int node = n0 + grp;
        if (node < n_nodes) xs[grp][c] = x[(size_t)node * CH + c];
        __syncthreads();
        if (node < n_nodes) {
            const ulonglong2* xp = (const ulonglong2*)xs[grp];
            u64 a0 = 0ull, a1 = 0ull, b0 = 0ull, bacc1 = 0ull;
#pragma unroll
            for (int q = 0; q < 16; q++) {
                ulonglong2 xv = xp[q];
                a0    = fma2(xv.x, wa[2 * q],     a0);
                a1    = fma2(xv.y, wa[2 * q + 1], a1);
                b0    = fma2(xv.x, wb[2 * q],     b0);
                bacc1 = fma2(xv.y, wb[2 * q + 1], bacc1);
            }
            g_A[(size_t)node * CH + c] = hsum2(add2(a0, a1));
            g_B[(size_t)node * CH + c] = hsum2(add2(b0, bacc1)) + b1c;
        }
        __syncthreads();
    }
}

// ---------------------------------------------------------------------------
// Edge kernel v4: 128 threads = 2 slots x 64 ch; UN=3 edges per slot per iter.
// ---------------------------------------------------------------------------
__global__ void __launch_bounds__(128, 3) edge_kernel(
    const void* __restrict__ ei_raw,
    const float* __restrict__ ea,
    const float* __restrict__ W1,
    const float* __restrict__ gamma, const float* __restrict__ beta,
    const float* __restrict__ W2, const float* __restrict__ b2,
    float* __restrict__ out, int n_edges)
{
    const int t    = threadIdx.x;
    const int c    = t & 63;
    const int slot = t >> 6;
    const int hw   = (t >> 5) & 1;
    const int lead = t & 63;
    const int flag64 = g_idx64;

    u64 w1e[16], w2p[32];
#pragma unroll
    for (int q = 0; q < 16; q++)
        w1e[q] = pk2(W1[(128 + 2 * q) * CH + c], W1[(128 + 2 * q + 1) * CH + c]);
#pragma unroll
    for (int q = 0; q < 32; q++)
        w2p[q] = pk2(W2[(2 * q) * CH + c], W2[(2 * q + 1) * CH + c]);

    const float gmc = gamma[c], btc = beta[c], b2c = b2[c];

    __shared__ __align__(16) float ea_s[2][3][UN][ED];   // [slot][buf][u][k]
    __shared__ float2 sred[2][UN][2];
    __shared__ __align__(16) float gsh[2][UN][CH];
    __shared__ __align__(16) float msh[2][UN][CH];

    const long long* ei64 = (const long long*)ei_raw;
    const int*       ei32 = (const int*)ei_raw;
    const int estep = gridDim.x * 2 * UN;

    auto load_idx = [&](int ee, int& ii, int& jj) {
        if (flag64) { ii = (int)ei64[ee]; jj = (int)ei64[(size_t)n_edges + ee]; }
        else        { ii = ei32[ee];      jj = ei32[(size_t)n_edges + ee]; }
    };
    auto clampe = [&](int ee) { return (ee < n_edges) ? ee : 0; };

    // cp.async helper: stage ea rows of edges (ebase..ebase+UN) into buffer b.
    // 24 lead threads: u = lead>>3 (edge), v = lead&7 (16B chunk).
    auto stage_ea = [&](int ebase, int b) {
        if (lead < 8 * UN) {
            int u  = lead >> 3, v = lead & 7;
            int ee = clampe(ebase + u);
            cpasync16(&ea_s[slot][b][u][v * 4], ea + (size_t)ee * ED + v * 4);
        }
        cpasync_commit();
    };

    const int myoff = slot * UN;
    int e0 = blockIdx.x * 2 * UN;

    // ---------------- prologue ----------------
    int jc[UN];                      // current edges' scatter targets
    float Af[UN], Bf[UN];
    int i1[UN], j1[UN];              // iter+1 indices
    int i2[UN], j2[UN];              // iter+2 indices
#pragma unroll
    for (int u = 0; u < UN; u++) {
        int icur;
        load_idx(clampe(e0 + myoff + u), icur, jc[u]);
        Af[u] = g_A[(size_t)icur * CH + c];
        Bf[u] = g_B[(size_t)jc[u] * CH + c];
        load_idx(clampe(e0 + estep + myoff + u),     i1[u], j1[u]);
        load_idx(clampe(e0 + 2 * estep + myoff + u), i2[u], j2[u]);
    }
    stage_ea(e0 + myoff, 0);                 // iter 0
    stage_ea(e0 + estep + myoff, 1);         // iter 1
    cpasync_wait1();                         // iter-0 buffer complete
    __syncthreads();

    int buf = 0;
    for (; e0 < n_edges; e0 += estep) {
        // prefetch ea for iter+2 into third buffer
        stage_ea(e0 + 2 * estep + myoff, (buf + 2) % 3);

        // -------- phase 1: h[u] = A + B + ea.W1e (3 independent chains) ----
        float h[UN];
#pragma unroll
        for (int u = 0; u < UN; u++) {
            const ulonglong2* ep = (const ulonglong2*)ea_s[slot][buf][u];
            u64 a0 = 0ull, a1 = 0ull;
#pragma unroll
            for (int q = 0; q < 8; q++) {
                ulonglong2 v = ep[q];
                a0 = fma2(v.x, w1e[2 * q],     a0);
                a1 = fma2(v.y, w1e[2 * q + 1], a1);
            }
            h[u] = Af[u] + Bf[u] + hsum2(add2(a0, a1));
        }

        // -------- prefetch A/B for iter+1 (indices arrived 2 iters ago) ----
        float Anx[UN], Bnx[UN];
#pragma unroll
        for (int u = 0; u < UN; u++) {
            Anx[u] = g_A[(size_t)i1[u] * CH + c];
            Bnx[u] = g_B[(size_t)j1[u] * CH + c];
        }

        // -------- LN stats: packed (s, s2), 3 interleaved butterflies ------
        u64 ss[UN];
#pragma unroll
        for (int u = 0; u < UN; u++) ss[u] = pk2(h[u], h[u] * h[u]);
#pragma unroll
        for (int o = 16; o; o >>= 1) {
#pragma unroll
            for (int u = 0; u < UN; u++)
                ss[u] = add2(ss[u], __shfl_xor_sync(0xffffffffu, ss[u], o));
        }
        if ((t & 31) == 0) {
#pragma unroll
            for (int u = 0; u < UN; u++) {
                float a, b; unpk2(ss[u], a, b);
                sred[slot][u][hw] = make_float2(a, b);
            }
        }
        __syncthreads();                                   // sync1

        // -------- phase 2: LN + exact GELU (3 independent) -----------------
#pragma unroll
        for (int u = 0; u < UN; u++) {
            const float2 p0 = sred[slot][u][0];
            const float2 p1 = sred[slot][u][1];
            const float mean = (p0.x + p1.x) * (1.0f / 64.0f);
            const float m2   = (p0.y + p1.y) * (1.0f / 64.0f);
            const float rstd = rsqrtf(m2 - mean * mean + 1e-5f);
            const float hn   = (h[u] - mean) * rstd * gmc + btc;
            gsh[slot][u][c]  = 0.5f * hn *
                               (1.0f + erff(hn * 0.70710678118654752440f));
        }
        __syncthreads();                                   // sync2

        // -------- phase 3: m[u] = g.W2 + b2 (3 chains interleaved) ---------
#pragma unroll
        for (int u = 0; u < UN; u++) {
            const ulonglong2* gp = (const ulonglong2*)gsh[slot][u];
            u64 a0 = 0ull, a1 = 0ull;
#pragma unroll
            for (int q = 0; q < 16; q++) {
                ulonglong2 v = gp[q];
                a0 = fma2(v.x, w2p[2 * q],     a0);
                a1 = fma2(v.y, w2p[2 * q + 1], a1);
            }
            msh[slot][u][c] = hsum2(add2(a0, a1)) + b2c;
        }
        cpasync_wait1();            // iter+1 ea buffer complete before sync3
        __syncthreads();                                   // sync3

        // -------- phase 4: vector scatter-add ------------------------------
        if (lead < 16) {
#pragma unroll
            for (int u = 0; u < UN; u++) {
                if (e0 + myoff + u < n_edges) {
                    float4 mv = ((const float4*)msh[slot][u])[lead];
                    red4(out + (size_t)jc[u] * CH + 4 * lead, mv);
                }
            }
        }

        // -------- rotate pipeline ------------------------------------------
#pragma unroll
        for (int u = 0; u < UN; u++) {
            Af[u] = Anx[u]; Bf[u] = Bnx[u];
            jc[u] = j1[u];
            i1[u] = i2[u];  j1[u] = j2[u];
            load_idx(clampe(e0 + 3 * estep + myoff + u), i2[u], j2[u]);
        }
        buf = (buf + 1) % 3;
    }
}

// ---------------------------------------------------------------------------
// Inputs: x[N,64] f32, edge_index[2,E] (i32/i64), edge_attr[E,32] f32,
// W1[160,64], b1[64], gamma[64], beta[64], W2[64,64], b2[64]. Out [N,64] f32.
// ---------------------------------------------------------------------------
extern "C" void kernel_launch(void* const* d_in, const int* in_sizes, int n_in,
                              void* d_out, int out_size)
{
    const float* x     = (const float*)d_in[0];
    const void*  ei    = d_in[1];
    const float* ea    = (const float*)d_in[2];
    const float* W1    = (const float*)d_in[3];
    const float* b1    = (const float*)d_in[4];
    const float* gamma = (const float*)d_in[5];
    const float* beta  = (const float*)d_in[6];
    const float* W2    = (const float*)d_in[7];
    const float* b2    = (const float*)d_in[8];
    float* out = (float*)d_out;

    const int n_nodes = in_sizes[0] / CH;
    const int n_edges = in_sizes[2] / ED;
    if (n_nodes > MAXN) return;

    cudaMemsetAsync(d_out, 0, (size_t)out_size * sizeof(float));

    int npre_blocks = (n_nodes + 3) / 4;
    if (npre_blocks > 1024) npre_blocks = 1024;
    node_pre_kernel<<<npre_blocks, 256>>>(x, W1, b1, (const int*)ei, n_nodes);

    edge_kernel<<<1332, 128>>>(ei, ea, W1, gamma, beta, W2, b2, out, n_edges);
}

// round 9
// speedup vs baseline: 5.2110x; 2.2244x over previous
#include <cuda_runtime.h>
#include <cuda_bf16.h>
#include <math.h>

// ===========================================================================
// MPConv via mma.sync bf16 (sm_80+ path, works at compute_103):
//   node precompute: A = x@W1[0:64], B = x@W1[64:128]+b1   (scalar, f32x2)
//   edge (warp-autonomous 32-edge tiles, no in-loop barriers):
//     acc1 = A[i]+B[j]  (fragment-layout gather, init of C)
//     acc1 += ea @ W1e  (3-term split-bf16 mma.sync, K=32)
//     LN per row (quad shfl only) + exact-erf GELU, in registers
//     acc2 = b2 ; acc2 += g @ W2 (3-term split-bf16, K=64)
//     red.global.add.v2 scatter from fragments
// ===========================================================================

#define MAXN 100000
#define CH   64
#define ED   32

__device__ float g_A[(size_t)MAXN * CH];
__device__ float g_B[(size_t)MAXN * CH];
__device__ int   g_idx64;

typedef unsigned long long u64;
typedef unsigned int       u32;

__device__ __forceinline__ u64 pk2(float lo, float hi) {
    u64 r; asm("mov.b64 %0, {%1,%2};" : "=l"(r) : "f"(lo), "f"(hi)); return r;
}
__device__ __forceinline__ void unpk2(u64 v, float& lo, float& hi) {
    asm("mov.b64 {%0,%1}, %2;" : "=f"(lo), "=f"(hi) : "l"(v));
}
__device__ __forceinline__ u64 fma2(u64 a, u64 b, u64 c) {
    u64 d; asm("fma.rn.f32x2 %0, %1, %2, %3;" : "=l"(d) : "l"(a), "l"(b), "l"(c));
    return d;
}
__device__ __forceinline__ u64 add2(u64 a, u64 b) {
    u64 d; asm("add.rn.f32x2 %0, %1, %2;" : "=l"(d) : "l"(a), "l"(b));
    return d;
}
__device__ __forceinline__ float hsum2(u64 v) { float a, b; unpk2(v, a, b); return a + b; }

__device__ __forceinline__ void red2(float* p, float x, float y) {
    asm volatile("red.global.add.v2.f32 [%0], {%1,%2};"
                 :: "l"(p), "f"(x), "f"(y) : "memory");
}
__device__ __forceinline__ void split1(float v, __nv_bfloat16& h, __nv_bfloat16& l) {
    h = __float2bfloat16_rn(v);
    l = __float2bfloat16_rn(v - __bfloat162float(h));
}
__device__ __forceinline__ u32 pkbf(__nv_bfloat16 a, __nv_bfloat16 b) {
    __nv_bfloat162 t(a, b); return *(u32*)&t;
}

// D += A(m16k16,row) * B(k16n8,col)  bf16 -> f32
__device__ __forceinline__ void mma16816(float* c, const u32* a, const u32* b) {
    asm volatile(
        "mma.sync.aligned.m16n8k16.row.col.f32.bf16.bf16.f32 "
        "{%0,%1,%2,%3}, {%4,%5,%6,%7}, {%8,%9}, {%0,%1,%2,%3};"
        : "+f"(c[0]), "+f"(c[1]), "+f"(c[2]), "+f"(c[3])
        : "r"(a[0]), "r"(a[1]), "r"(a[2]), "r"(a[3]), "r"(b[0]), "r"(b[1]));
}

// ---------------------------------------------------------------------------
// Node precompute (+ idx-width detection in block 0)
// ---------------------------------------------------------------------------
__global__ __launch_bounds__(256) void node_pre_kernel(
    const float* __restrict__ x, const float* __restrict__ W1,
    const float* __restrict__ b1, const int* __restrict__ ei, int n_nodes)
{
    const int t = threadIdx.x, c = t & 63, grp = t >> 6;

    if (blockIdx.x == 0) {
        int ok = 1;
        for (int q = t; q < 1024; q += blockDim.x)
            if (ei[2 * q + 1] != 0) ok = 0;
        ok = __syncthreads_and(ok);
        if (t == 0) g_idx64 = ok;
    }

    u64 wa[32], wb[32];
#pragma unroll
    for (int q = 0; q < 32; q++) {
        wa[q] = pk2(W1[(2 * q) * CH + c],      W1[(2 * q + 1) * CH + c]);
        wb[q] = pk2(W1[(64 + 2 * q) * CH + c], W1[(64 + 2 * q + 1) * CH + c]);
    }
    const float b1c = b1[c];
    __shared__ __align__(16) float xs[4][CH];

    for (int n0 = blockIdx.x * 4; n0 < n_nodes; n0 += gridDim.x * 4) {
        const int node = n0 + grp;
        if (node < n_nodes) xs[grp][c] = x[(size_t)node * CH + c];
        __syncthreads();
        if (node < n_nodes) {
            const ulonglong2* xp = (const ulonglong2*)xs[grp];
            u64 a0 = 0ull, a1 = 0ull, b0 = 0ull, bb = 0ull;
#pragma unroll
            for (int q = 0; q < 16; q++) {
                ulonglong2 xv = xp[q];
                a0 = fma2(xv.x, wa[2 * q],     a0);
                a1 = fma2(xv.y, wa[2 * q + 1], a1);
                b0 = fma2(xv.x, wb[2 * q],     b0);
                bb = fma2(xv.y, wb[2 * q + 1], bb);
            }
            g_A[(size_t)node * CH + c] = hsum2(add2(a0, a1));
            g_B[(size_t)node * CH + c] = hsum2(add2(b0, bb)) + b1c;
        }
        __syncthreads();
    }
}

// ---------------------------------------------------------------------------
// Edge kernel: 128 threads = 4 independent warps, each owning 32-edge tiles.
// ---------------------------------------------------------------------------
__global__ void __launch_bounds__(128) edge_mma_kernel(
    const void* __restrict__ ei_raw,
    const float* __restrict__ ea,
    const float* __restrict__ W1,
    const float* __restrict__ gamma, const float* __restrict__ beta,
    const float* __restrict__ W2, const float* __restrict__ b2,
    float* __restrict__ out, int n_edges, int n_wtiles)
{
    // Weights as bf16 k-pair words; pad strides 20/36 -> conflict-free B LDS.
    __shared__ u32 sW1H[64][20], sW1L[64][20];
    __shared__ u32 sW2H[64][36], sW2L[64][36];
    __shared__ float sgm[64], sbt[64], sb2v[64];

    const int tid = threadIdx.x;
    for (int idx = tid; idx < 64 * 16; idx += 128) {
        int n = idx >> 4, p = idx & 15;
        __nv_bfloat16 h0, l0, h1, l1;
        split1(W1[(size_t)(128 + 2 * p) * CH + n], h0, l0);
        split1(W1[(size_t)(128 + 2 * p + 1) * CH + n], h1, l1);
        sW1H[n][p] = pkbf(h0, h1);
        sW1L[n][p] = pkbf(l0, l1);
    }
    for (int idx = tid; idx < 64 * 32; idx += 128) {
        int n = idx >> 5, p = idx & 31;
        __nv_bfloat16 h0, l0, h1, l1;
        split1(W2[(size_t)(2 * p) * CH + n], h0, l0);
        split1(W2[(size_t)(2 * p + 1) * CH + n], h1, l1);
        sW2H[n][p] = pkbf(h0, h1);
        sW2L[n][p] = pkbf(l0, l1);
    }
    if (tid < 64) { sgm[tid] = gamma[tid]; sbt[tid] = beta[tid]; sb2v[tid] = b2[tid]; }
    __syncthreads();

    const int wid = tid >> 5, lane = tid & 31;
    const int q = lane >> 2, tq = lane & 3;
    const int flag64 = g_idx64;
    const long long* ei64 = (const long long*)ei_raw;
    const int*       ei32 = (const int*)ei_raw;

    for (int wt = blockIdx.x * 4 + wid; wt < n_wtiles; wt += gridDim.x * 4) {
        const int eb = wt * 32;

        // ---- indices for this thread's 4 rows: r = 16*mt + 8*g8 + q ------
        int iv[4], jv[4];
#pragma unroll
        for (int r4 = 0; r4 < 4; r4++) {
            int row = ((r4 >> 1) << 4) + ((r4 & 1) << 3) + q;
            int e = eb + row; if (e >= n_edges) e = 0;
            if (flag64) { iv[r4] = (int)ei64[e]; jv[r4] = (int)ei64[(size_t)n_edges + e]; }
            else        { iv[r4] = ei32[e];      jv[r4] = ei32[(size_t)n_edges + e]; }
        }

        // ---- acc1 init = s = A[i]+B[j]  (fragment-layout gather) ---------
        float acc[2][8][4];
#pragma unroll
        for (int mt = 0; mt < 2; mt++) {
            const float2* pa0 = (const float2*)(g_A + (size_t)iv[2 * mt]     * CH);
            const float2* pb0 = (const float2*)(g_B + (size_t)jv[2 * mt]     * CH);
            const float2* pa8 = (const float2*)(g_A + (size_t)iv[2 * mt + 1] * CH);
            const float2* pb8 = (const float2*)(g_B + (size_t)jv[2 * mt + 1] * CH);
#pragma unroll
            for (int nt = 0; nt < 8; nt++) {
                float2 x0 = pa0[4 * nt + tq], y0 = pb0[4 * nt + tq];
                float2 x8 = pa8[4 * nt + tq], y8 = pb8[4 * nt + tq];
                acc[mt][nt][0] = x0.x + y0.x;  acc[mt][nt][1] = x0.y + y0.y;
                acc[mt][nt][2] = x8.x + y8.x;  acc[mt][nt][3] = x8.y + y8.y;
            }
        }

        // ---- ea A-fragments (split hi/lo) --------------------------------
        // a[gr*2+g8]: a0=(r0,k grp0) a1=(r8,grp0) a2=(r0,grp1) a3=(r8,grp1)
        u32 eH[2][2][4], eL[2][2][4];
#pragma unroll
        for (int mt = 0; mt < 2; mt++)
#pragma unroll
            for (int g8 = 0; g8 < 2; g8++) {
                int row = mt * 16 + g8 * 8 + q;
                int e = eb + row; if (e >= n_edges) e = 0;
                const float2* pe = (const float2*)(ea + (size_t)e * ED);
#pragma unroll
                for (int kt = 0; kt < 2; kt++)
#pragma unroll
                    for (int gr = 0; gr < 2; gr++) {
                        float2 v = pe[8 * kt + 4 * gr + tq];
                        __nv_bfloat16 hx, lx, hy, ly;
                        split1(v.x, hx, lx); split1(v.y, hy, ly);
                        eH[mt][kt][gr * 2 + g8] = pkbf(hx, hy);
                        eL[mt][kt][gr * 2 + g8] = pkbf(lx, ly);
                    }
            }

        // ---- GEMM1: acc += ea @ W1e  (3-term split) ----------------------
#pragma unroll
        for (int kt = 0; kt < 2; kt++)
#pragma unroll
            for (int nt = 0; nt < 8; nt++) {
                int nr = 8 * nt + q;
                u32 bH[2] = { sW1H[nr][8 * kt + tq], sW1H[nr][8 * kt + tq + 4] };
                u32 bL[2] = { sW1L[nr][8 * kt + tq], sW1L[nr][8 * kt + tq + 4] };
#pragma unroll
                for (int mt = 0; mt < 2; mt++) {
                    mma16816(acc[mt][nt], eH[mt][kt], bH);
                    mma16816(acc[mt][nt], eH[mt][kt], bL);
                    mma16816(acc[mt][nt], eL[mt][kt], bH);
                }
            }

        // ---- LayerNorm stats: quad reduce (2 shfl) per row ---------------
        float mean[2][2], rstd[2][2];
#pragma unroll
        for (int mt = 0; mt < 2; mt++)
#pragma unroll
            for (int g8 = 0; g8 < 2; g8++) {
                u64 ssp = 0ull;
#pragma unroll
                for (int nt = 0; nt < 8; nt++) {
                    float v0 = acc[mt][nt][2 * g8], v1 = acc[mt][nt][2 * g8 + 1];
                    ssp = add2(ssp, pk2(v0 + v1, fmaf(v0, v0, v1 * v1)));
                }
                ssp = add2(ssp, __shfl_xor_sync(0xffffffffu, ssp, 1));
                ssp = add2(ssp, __shfl_xor_sync(0xffffffffu, ssp, 2));
                float s, s2; unpk2(ssp, s, s2);
                float mu = s * (1.0f / 64.0f);
                mean[mt][g8] = mu;
                rstd[mt][g8] = rsqrtf(s2 * (1.0f / 64.0f) - mu * mu + 1e-5f);
            }

        // ---- LN + exact GELU + split -> GEMM2 A-fragments ----------------
        u32 gh[2][2][8], gl[2][2][8];     // [mt][g8][nt]
#pragma unroll
        for (int mt = 0; mt < 2; mt++)
#pragma unroll
            for (int nt = 0; nt < 8; nt++) {
                float2 gm = *(const float2*)&sgm[8 * nt + 2 * tq];
                float2 bt = *(const float2*)&sbt[8 * nt + 2 * tq];
#pragma unroll
                for (int g8 = 0; g8 < 2; g8++) {
                    float h0 = fmaf((acc[mt][nt][2 * g8]     - mean[mt][g8]) * rstd[mt][g8], gm.x, bt.x);
                    float h1 = fmaf((acc[mt][nt][2 * g8 + 1] - mean[mt][g8]) * rstd[mt][g8], gm.y, bt.y);
                    float e0 = 0.5f * h0 * (1.0f + erff(h0 * 0.70710678118654752440f));
                    float e1 = 0.5f * h1 * (1.0f + erff(h1 * 0.70710678118654752440f));
                    __nv_bfloat16 hh0, ll0, hh1, ll1;
                    split1(e0, hh0, ll0); split1(e1, hh1, ll1);
                    gh[mt][g8][nt] = pkbf(hh0, hh1);
                    gl[mt][g8][nt] = pkbf(ll0, ll1);
                }
            }

        // ---- GEMM2: acc2 = b2 + g @ W2  (3-term split) -------------------
        float acc2[2][8][4];
#pragma unroll
        for (int mt = 0; mt < 2; mt++)
#pragma unroll
            for (int nt = 0; nt < 8; nt++) {
                float2 b2p = *(const float2*)&sb2v[8 * nt + 2 * tq];
                acc2[mt][nt][0] = b2p.x; acc2[mt][nt][1] = b2p.y;
                acc2[mt][nt][2] = b2p.x; acc2[mt][nt][3] = b2p.y;
            }
#pragma unroll
        for (int kt = 0; kt < 4; kt++)
#pragma unroll
            for (int nt = 0; nt < 8; nt++) {
                int nr = 8 * nt + q;
                u32 bH[2] = { sW2H[nr][8 * kt + tq], sW2H[nr][8 * kt + tq + 4] };
                u32 bL[2] = { sW2L[nr][8 * kt + tq], sW2L[nr][8 * kt + tq + 4] };
#pragma unroll
                for (int mt = 0; mt < 2; mt++) {
                    u32 aH[4] = { gh[mt][0][2 * kt], gh[mt][1][2 * kt],
                                  gh[mt][0][2 * kt + 1], gh[mt][1][2 * kt + 1] };
                    u32 aL[4] = { gl[mt][0][2 * kt], gl[mt][1][2 * kt],
                                  gl[mt][0][2 * kt + 1], gl[mt][1][2 * kt + 1] };
                    mma16816(acc2[mt][nt], aH, bH);
                    mma16816(acc2[mt][nt], aH, bL);
                    mma16816(acc2[mt][nt], aL, bH);
                }
            }

        // ---- scatter straight from fragments -----------------------------
#pragma unroll
        for (int mt = 0; mt < 2; mt++)
#pragma unroll
            for (int g8 = 0; g8 < 2; g8++) {
                int row = mt * 16 + g8 * 8 + q;
                int e = eb + row;
                if (e < n_edges) {
                    float* op = out + (size_t)jv[2 * mt + g8] * CH + 2 * tq;
#pragma unroll
                    for (int nt = 0; nt < 8; nt++)
                        red2(op + 8 * nt, acc2[mt][nt][2 * g8], acc2[mt][nt][2 * g8 + 1]);
                }
            }
    }
}

// ---------------------------------------------------------------------------
// Inputs: x[N,64] f32, edge_index[2,E] (i32/i64), edge_attr[E,32] f32,
// W1[160,64], b1[64], gamma[64], beta[64], W2[64,64], b2[64]. Out [N,64] f32.
// ---------------------------------------------------------------------------
extern "C" void kernel_launch(void* const* d_in, const int* in_sizes, int n_in,
                              void* d_out, int out_size)
{
    const float* x     = (const float*)d_in[0];
    const void*  ei    = d_in[1];
    const float* ea    = (const float*)d_in[2];
    const float* W1    = (const float*)d_in[3];
    const float* b1    = (const float*)d_in[4];
    const float* gamma = (const float*)d_in[5];
    const float* beta  = (const float*)d_in[6];
    const float* W2    = (const float*)d_in[7];
    const float* b2    = (const float*)d_in[8];
    float* out = (float*)d_out;

    const int n_nodes  = in_sizes[0] / CH;
    const int n_edges  = in_sizes[2] / ED;
    const int n_wtiles = (n_edges + 31) / 32;
    if (n_nodes > MAXN) return;

    cudaMemsetAsync(d_out, 0, (size_t)out_size * sizeof(float));

    int npre_blocks = (n_nodes + 3) / 4;
    if (npre_blocks > 1024) npre_blocks = 1024;
    node_pre_kernel<<<npre_blocks, 256>>>(x, W1, b1, (const int*)ei, n_nodes);

    edge_mma_kernel<<<296, 128>>>(ei, ea, W1, gamma, beta, W2, b2,
                                  out, n_edges, n_wtiles);
}

// round 10
// speedup vs baseline: 5.6140x; 1.0773x over previous
#include <cuda_runtime.h>
#include <cuda_bf16.h>
#include <math.h>

// ===========================================================================
// MPConv via mma.sync bf16 (compute_103-safe):
//   node precompute: A = x@W1[0:64], B = x@W1[64:128]+b1  (scalar f32x2,
//     thread owns ONE of A/B -> half the weight registers, 2x occupancy)
//   edge (warp-autonomous 32-edge tiles, no in-loop barriers):
//     acc1 = A[i]+B[j] (fragment gather) ; acc1 += ea@W1e (3-term split-bf16)
//     LN per row (2 quad shfl) + exact-erf GELU in registers
//     GEMM2 g@W2+b2 in TWO sequential N-halves (register diet -> 3 blocks/SM)
//     red.global.add.v2 scatter from fragments
// ===========================================================================

#define MAXN 100000
#define CH   64
#define ED   32

__device__ float g_A[(size_t)MAXN * CH];
__device__ float g_B[(size_t)MAXN * CH];
__device__ int   g_idx64;

typedef unsigned long long u64;
typedef unsigned int       u32;

__device__ __forceinline__ u64 pk2(float lo, float hi) {
    u64 r; asm("mov.b64 %0, {%1,%2};" : "=l"(r) : "f"(lo), "f"(hi)); return r;
}
__device__ __forceinline__ void unpk2(u64 v, float& lo, float& hi) {
    asm("mov.b64 {%0,%1}, %2;" : "=f"(lo), "=f"(hi) : "l"(v));
}
__device__ __forceinline__ u64 fma2(u64 a, u64 b, u64 c) {
    u64 d; asm("fma.rn.f32x2 %0, %1, %2, %3;" : "=l"(d) : "l"(a), "l"(b), "l"(c));
    return d;
}
__device__ __forceinline__ u64 add2(u64 a, u64 b) {
    u64 d; asm("add.rn.f32x2 %0, %1, %2;" : "=l"(d) : "l"(a), "l"(b));
    return d;
}
__device__ __forceinline__ float hsum2(u64 v) { float a, b; unpk2(v, a, b); return a + b; }

__device__ __forceinline__ void red2(float* p, float x, float y) {
    asm volatile("red.global.add.v2.f32 [%0], {%1,%2};"
                 :: "l"(p), "f"(x), "f"(y) : "memory");
}
__device__ __forceinline__ void split1(float v, __nv_bfloat16& h, __nv_bfloat16& l) {
    h = __float2bfloat16_rn(v);
    l = __float2bfloat16_rn(v - __bfloat162float(h));
}
__device__ __forceinline__ u32 pkbf(__nv_bfloat16 a, __nv_bfloat16 b) {
    __nv_bfloat162 t(a, b); return *(u32*)&t;
}

// D += A(m16k16,row) * B(k16n8,col)  bf16 -> f32
__device__ __forceinline__ void mma16816(float* c, const u32* a, const u32* b) {
    asm volatile(
        "mma.sync.aligned.m16n8k16.row.col.f32.bf16.bf16.f32 "
        "{%0,%1,%2,%3}, {%4,%5,%6,%7}, {%8,%9}, {%0,%1,%2,%3};"
        : "+f"(c[0]), "+f"(c[1]), "+f"(c[2]), "+f"(c[3])
        : "r"(a[0]), "r"(a[1]), "r"(a[2]), "r"(a[3]), "r"(b[0]), "r"(b[1]));
}

// ---------------------------------------------------------------------------
// Node precompute: 256 thr = 2 nodes x {A,B} x 64 ch. 64 weight regs/thread.
// ---------------------------------------------------------------------------
__global__ __launch_bounds__(256) void node_pre_kernel(
    const float* __restrict__ x, const float* __restrict__ W1,
    const float* __restrict__ b1, const int* __restrict__ ei, int n_nodes)
{
    const int t = threadIdx.x;
    const int c   = t & 63;
    const int ab  = (t >> 6) & 1;       // 0 -> A, 1 -> B
    const int grp = t >> 7;             // node within pair

    if (blockIdx.x == 0) {
        int ok = 1;
        for (int q = t; q < 1024; q += blockDim.x)
            if (ei[2 * q + 1] != 0) ok = 0;
        ok = __syncthreads_and(ok);
        if (t == 0) g_idx64 = ok;
    }

    const int kofs = ab ? 64 : 0;
    u64 w[32];
#pragma unroll
    for (int q = 0; q < 32; q++)
        w[q] = pk2(W1[(kofs + 2 * q) * CH + c], W1[(kofs + 2 * q + 1) * CH + c]);
    const float bias = ab ? b1[c] : 0.0f;
    float* dst = ab ? g_B : g_A;

    __shared__ __align__(16) float xs[2][CH];

    for (int n0 = blockIdx.x * 2; n0 < n_nodes; n0 += gridDim.x * 2) {
        const int node = n0 + grp;
        if (ab == 0 && node < n_nodes) xs[grp][c] = x[(size_t)node * CH + c];
        __syncthreads();
        if (node < n_nodes) {
            const ulonglong2* xp = (const ulonglong2*)xs[grp];
            u64 a0 = 0ull, a1 = 0ull;
#pragma unroll
            for (int q = 0; q < 16; q++) {
                ulonglong2 xv = xp[q];
                a0 = fma2(xv.x, w[2 * q],     a0);
                a1 = fma2(xv.y, w[2 * q + 1], a1);
            }
            dst[(size_t)node * CH + c] = hsum2(add2(a0, a1)) + bias;
        }
        __syncthreads();
    }
}

// ---------------------------------------------------------------------------
// Edge kernel: 4 independent warps/block, each owning 32-edge tiles.
// ---------------------------------------------------------------------------
__global__ void __launch_bounds__(128, 3) edge_mma_kernel(
    const void* __restrict__ ei_raw,
    const float* __restrict__ ea,
    const float* __restrict__ W1,
    const float* __restrict__ gamma, const float* __restrict__ beta,
    const float* __restrict__ W2, const float* __restrict__ b2,
    float* __restrict__ out, int n_edges, int n_wtiles)
{
    // Weights as bf16 k-pair words; pad strides 20/36 -> conflict-free LDS.
    __shared__ u32 sW1H[64][20], sW1L[64][20];
    __shared__ u32 sW2H[64][36], sW2L[64][36];
    __shared__ float sgm[64], sbt[64], sb2v[64];

    const int tid = threadIdx.x;
    for (int idx = tid; idx < 64 * 16; idx += 128) {
        int n = idx >> 4, p = idx & 15;
        __nv_bfloat16 h0, l0, h1, l1;
        split1(W1[(size_t)(128 + 2 * p) * CH + n], h0, l0);
        split1(W1[(size_t)(128 + 2 * p + 1) * CH + n], h1, l1);
        sW1H[n][p] = pkbf(h0, h1);
        sW1L[n][p] = pkbf(l0, l1);
    }
    for (int idx = tid; idx < 64 * 32; idx += 128) {
        int n = idx >> 5, p = idx & 31;
        __nv_bfloat16 h0, l0, h1, l1;
        split1(W2[(size_t)(2 * p) * CH + n], h0, l0);
        split1(W2[(size_t)(2 * p + 1) * CH + n], h1, l1);
        sW2H[n][p] = pkbf(h0, h1);
        sW2L[n][p] = pkbf(l0, l1);
    }
    if (tid < 64) { sgm[tid] = gamma[tid]; sbt[tid] = beta[tid]; sb2v[tid] = b2[tid]; }
    __syncthreads();

    const int wid = tid >> 5, lane = tid & 31;
    const int q = lane >> 2, tq = lane & 3;
    const int flag64 = g_idx64;
    const long long* ei64 = (const long long*)ei_raw;
    const int*       ei32 = (const int*)ei_raw;

    for (int wt = blockIdx.x * 4 + wid; wt < n_wtiles; wt += gridDim.x * 4) {
        const int eb = wt * 32;

        // ---- indices: rows r = 16*mt + 8*g8 + q --------------------------
        int iv[4], jv[4];
#pragma unroll
        for (int r4 = 0; r4 < 4; r4++) {
            int row = ((r4 >> 1) << 4) + ((r4 & 1) << 3) + q;
            int e = eb + row; if (e >= n_edges) e = 0;
            if (flag64) { iv[r4] = (int)ei64[e]; jv[r4] = (int)ei64[(size_t)n_edges + e]; }
            else        { iv[r4] = ei32[e];      jv[r4] = ei32[(size_t)n_edges + e]; }
        }

        // ---- acc1 init = s = A[i]+B[j] (fragment-layout gather) ----------
        float acc[2][8][4];
#pragma unroll
        for (int mt = 0; mt < 2; mt++) {
            const float2* pa0 = (const float2*)(g_A + (size_t)iv[2 * mt]     * CH);
            const float2* pb0 = (const float2*)(g_B + (size_t)jv[2 * mt]     * CH);
            const float2* pa8 = (const float2*)(g_A + (size_t)iv[2 * mt + 1] * CH);
            const float2* pb8 = (const float2*)(g_B + (size_t)jv[2 * mt + 1] * CH);
#pragma unroll
            for (int nt = 0; nt < 8; nt++) {
                float2 x0 = pa0[4 * nt + tq], y0 = pb0[4 * nt + tq];
                float2 x8 = pa8[4 * nt + tq], y8 = pb8[4 * nt + tq];
                acc[mt][nt][0] = x0.x + y0.x;  acc[mt][nt][1] = x0.y + y0.y;
                acc[mt][nt][2] = x8.x + y8.x;  acc[mt][nt][3] = x8.y + y8.y;
            }
        }

        // ---- ea A-fragments (split hi/lo) --------------------------------
        u32 eH[2][2][4], eL[2][2][4];
#pragma unroll
        for (int mt = 0; mt < 2; mt++)
#pragma unroll
            for (int g8 = 0; g8 < 2; g8++) {
                int row = mt * 16 + g8 * 8 + q;
                int e = eb + row; if (e >= n_edges) e = 0;
                const float2* pe = (const float2*)(ea + (size_t)e * ED);
#pragma unroll
                for (int kt = 0; kt < 2; kt++)
#pragma unroll
                    for (int gr = 0; gr < 2; gr++) {
                        float2 v = pe[8 * kt + 4 * gr + tq];
                        __nv_bfloat16 hx, lx, hy, ly;
                        split1(v.x, hx, lx); split1(v.y, hy, ly);
                        eH[mt][kt][gr * 2 + g8] = pkbf(hx, hy);
                        eL[mt][kt][gr * 2 + g8] = pkbf(lx, ly);
                    }
            }

        // ---- GEMM1: acc += ea @ W1e (3-term split) -----------------------
#pragma unroll
        for (int kt = 0; kt < 2; kt++)
#pragma unroll
            for (int nt = 0; nt < 8; nt++) {
                int nr = 8 * nt + q;
                u32 bH[2] = { sW1H[nr][8 * kt + tq], sW1H[nr][8 * kt + tq + 4] };
                u32 bL[2] = { sW1L[nr][8 * kt + tq], sW1L[nr][8 * kt + tq + 4] };
#pragma unroll
                for (int mt = 0; mt < 2; mt++) {
                    mma16816(acc[mt][nt], eH[mt][kt], bH);
                    mma16816(acc[mt][nt], eH[mt][kt], bL);
                    mma16816(acc[mt][nt], eL[mt][kt], bH);
                }
            }

        // ---- LayerNorm stats: quad reduce (2 shfl) per row ---------------
        float mean[2][2], rstd[2][2];
#pragma unroll
        for (int mt = 0; mt < 2; mt++)
#pragma unroll
            for (int g8 = 0; g8 < 2; g8++) {
                u64 ssp = 0ull;
#pragma unroll
                for (int nt = 0; nt < 8; nt++) {
                    float v0 = acc[mt][nt][2 * g8], v1 = acc[mt][nt][2 * g8 + 1];
                    ssp = add2(ssp, pk2(v0 + v1, fmaf(v0, v0, v1 * v1)));
                }
                ssp = add2(ssp, __shfl_xor_sync(0xffffffffu, ssp, 1));
                ssp = add2(ssp, __shfl_xor_sync(0xffffffffu, ssp, 2));
                float s, s2; unpk2(ssp, s, s2);
                float mu = s * (1.0f / 64.0f);
                mean[mt][g8] = mu;
                rstd[mt][g8] = rsqrtf(s2 * (1.0f / 64.0f) - mu * mu + 1e-5f);
            }

        // ---- LN + exact GELU + split -> GEMM2 A-fragments ----------------
        u32 gh[2][2][8], gl[2][2][8];     // [mt][g8][nt]
#pragma unroll
        for (int mt = 0; mt < 2; mt++)
#pragma unroll
            for (int nt = 0; nt < 8; nt++) {
                float2 gm = *(const float2*)&sgm[8 * nt + 2 * tq];
                float2 bt = *(const float2*)&sbt[8 * nt + 2 * tq];
#pragma unroll
                for (int g8 = 0; g8 < 2; g8++) {
                    float h0 = fmaf((acc[mt][nt][2 * g8]     - mean[mt][g8]) * rstd[mt][g8], gm.x, bt.x);
                    float h1 = fmaf((acc[mt][nt][2 * g8 + 1] - mean[mt][g8]) * rstd[mt][g8], gm.y, bt.y);
                    float e0 = 0.5f * h0 * (1.0f + erff(h0 * 0.70710678118654752440f));
                    float e1 = 0.5f * h1 * (1.0f + erff(h1 * 0.70710678118654752440f));
                    __nv_bfloat16 hh0, ll0, hh1, ll1;
                    split1(e0, hh0, ll0); split1(e1, hh1, ll1);
                    gh[mt][g8][nt] = pkbf(hh0, hh1);
                    gl[mt][g8][nt] = pkbf(ll0, ll1);
                }
            }

        // ---- GEMM2 + scatter in TWO sequential N-halves (register diet) --
#pragma unroll 1
        for (int half = 0; half < 2; half++) {
            float acc2[2][4][4];
#pragma unroll
            for (int mt = 0; mt < 2; mt++)
#pragma unroll
                for (int n4 = 0; n4 < 4; n4++) {
                    int nt = half * 4 + n4;
                    float2 b2p = *(const float2*)&sb2v[8 * nt + 2 * tq];
                    acc2[mt][n4][0] = b2p.x; acc2[mt][n4][1] = b2p.y;
                    acc2[mt][n4][2] = b2p.x; acc2[mt][n4][3] = b2p.y;
                }
#pragma unroll
            for (int kt = 0; kt < 4; kt++)
#pragma unroll
                for (int n4 = 0; n4 < 4; n4++) {
                    int nt = half * 4 + n4;
                    int nr = 8 * nt + q;
                    u32 bH[2] = { sW2H[nr][8 * kt + tq], sW2H[nr][8 * kt + tq + 4] };
                    u32 bL[2] = { sW2L[nr][8 * kt + tq], sW2L[nr][8 * kt + tq + 4] };
#pragma unroll
                    for (int mt = 0; mt < 2; mt++) {
                        u32 aH[4] = { gh[mt][0][2 * kt], gh[mt][1][2 * kt],
                                      gh[mt][0][2 * kt + 1], gh[mt][1][2 * kt + 1] };
                        u32 aL[4] = { gl[mt][0][2 * kt], gl[mt][1][2 * kt],
                                      gl[mt][0][2 * kt + 1], gl[mt][1][2 * kt + 1] };
                        mma16816(acc2[mt][n4], aH, bH);
                        mma16816(acc2[mt][n4], aH, bL);
                        mma16816(acc2[mt][n4], aL, bH);
                    }
                }
#pragma unroll
            for (int mt = 0; mt < 2; mt++)
#pragma unroll
                for (int g8 = 0; g8 < 2; g8++) {
                    int row = mt * 16 + g8 * 8 + q;
                    int e = eb + row;
                    if (e < n_edges) {
                        float* op = out + (size_t)jv[2 * mt + g8] * CH + 2 * tq;
#pragma unroll
                        for (int n4 = 0; n4 < 4; n4++)
                            red2(op + 8 * (half * 4 + n4),
                                 acc2[mt][n4][2 * g8], acc2[mt][n4][2 * g8 + 1]);
                    }
                }
        }
    }
}

// ---------------------------------------------------------------------------
// Inputs: x[N,64] f32, edge_index[2,E] (i32/i64), edge_attr[E,32] f32,
// W1[160,64], b1[64], gamma[64], beta[64], W2[64,64], b2[64]. Out [N,64] f32.
// ---------------------------------------------------------------------------
extern "C" void kernel_launch(void* const* d_in, const int* in_sizes, int n_in,
                              void* d_out, int out_size)
{
    const float* x     = (const float*)d_in[0];
    const void*  ei    = d_in[1];
    const float* ea    = (const float*)d_in[2];
    const float* W1    = (const float*)d_in[3];
    const float* b1    = (const float*)d_in[4];
    const float* gamma = (const float*)d_in[5];
    const float* beta  = (const float*)d_in[6];
    const float* W2    = (const float*)d_in[7];
    const float* b2    = (const float*)d_in[8];
    float* out = (float*)d_out;

    const int n_nodes  = in_sizes[0] / CH;
    const int n_edges  = in_sizes[2] / ED;
    const int n_wtiles = (n_edges + 31) / 32;
    if (n_nodes > MAXN) return;

    cudaMemsetAsync(d_out, 0, (size_t)out_size * sizeof(float));

    node_pre_kernel<<<1184, 256>>>(x, W1, b1, (const int*)ei, n_nodes);

    edge_mma_kernel<<<444, 128>>>(ei, ea, W1, gamma, beta, W2, b2,
                                  out, n_edges, n_wtiles);
}

// round 11
// speedup vs baseline: 6.0309x; 1.0743x over previous
#include <cuda_runtime.h>
#include <cuda_bf16.h>
#include <math.h>

// ===========================================================================
// MPConv via mma.sync bf16 (compute_103-safe):
//   node precompute: A = x@W1[0:64], B = x@W1[64:128]+b1 (scalar f32x2)
//   edge (warp-autonomous 32-edge tiles, no in-loop barriers):
//     acc1 = A[i]+B[j] (fragment gather) ; acc1 += ea@W1e (3-term split-bf16)
//     LN per row (2 quad shfl) + FAST branchless erf-GELU (A&S 7.1.26)
//     GEMM2 g@W2+b2 in two sequential N-halves ; red.global.add.v2 scatter
//   v5: fast erf, prmt/cvt.bf16x2 splits, u64 weight LDS, idx prefetch.
// ===========================================================================

#define MAXN 100000
#define CH   64
#define ED   32

__device__ float g_A[(size_t)MAXN * CH];
__device__ float g_B[(size_t)MAXN * CH];
__device__ int   g_idx64;

typedef unsigned long long u64;
typedef unsigned int       u32;

__device__ __forceinline__ u64 pk2(float lo, float hi) {
    u64 r; asm("mov.b64 %0, {%1,%2};" : "=l"(r) : "f"(lo), "f"(hi)); return r;
}
__device__ __forceinline__ void unpk2(u64 v, float& lo, float& hi) {
    asm("mov.b64 {%0,%1}, %2;" : "=f"(lo), "=f"(hi) : "l"(v));
}
__device__ __forceinline__ u64 fma2(u64 a, u64 b, u64 c) {
    u64 d; asm("fma.rn.f32x2 %0, %1, %2, %3;" : "=l"(d) : "l"(a), "l"(b), "l"(c));
    return d;
}
__device__ __forceinline__ u64 add2(u64 a, u64 b) {
    u64 d; asm("add.rn.f32x2 %0, %1, %2;" : "=l"(d) : "l"(a), "l"(b));
    return d;
}
__device__ __forceinline__ float hsum2(u64 v) { float a, b; unpk2(v, a, b); return a + b; }

__device__ __forceinline__ void red2(float* p, float x, float y) {
    asm volatile("red.global.add.v2.f32 [%0], {%1,%2};"
                 :: "l"(p), "f"(x), "f"(y) : "memory");
}
__device__ __forceinline__ void split1(float v, __nv_bfloat16& h, __nv_bfloat16& l) {
    h = __float2bfloat16_rn(v);
    l = __float2bfloat16_rn(v - __bfloat162float(h));
}
__device__ __forceinline__ u32 pkbf(__nv_bfloat16 a, __nv_bfloat16 b) {
    __nv_bfloat162 t(a, b); return *(u32*)&t;
}

// Fast split: hi = mantissa-truncated bf16 (1 prmt for the pair),
// lo = exact residual rounded to bf16 (1 cvt.bf16x2 for the pair).
__device__ __forceinline__ u32 hi_pair(float x, float y) {
    u32 r;
    asm("prmt.b32 %0, %1, %2, 0x7632;"
        : "=r"(r) : "r"(__float_as_uint(x)), "r"(__float_as_uint(y)));
    return r;
}
__device__ __forceinline__ u32 lo_pair(float x, float y) {
    float lx = x - __uint_as_float(__float_as_uint(x) & 0xFFFF0000u);
    float ly = y - __uint_as_float(__float_as_uint(y) & 0xFFFF0000u);
    u32 r;
    asm("cvt.rn.bf16x2.f32 %0, %1, %2;" : "=r"(r) : "f"(ly), "f"(lx));
    return r;
}

// Branchless GELU with A&S 7.1.26 erf (|eps| <= 1.5e-7 abs):
//   gelu(x) = 0.5 x + 0.5 |x| * erf(|x|/sqrt(2))
__device__ __forceinline__ float gelu_fast(float x) {
    const float axo = fabsf(x);
    const float ax  = axo * 0.70710678118654752440f;
    float t;
    asm("rcp.approx.f32 %0, %1;" : "=f"(t) : "f"(fmaf(0.3275911f, ax, 1.0f)));
    float p = fmaf(1.061405429f, t, -1.453152027f);
    p = fmaf(p, t, 1.421413741f);
    p = fmaf(p, t, -0.284496736f);
    p = fmaf(p, t, 0.254829592f);
    p = p * t;
    float ex;
    asm("ex2.approx.f32 %0, %1;"
        : "=f"(ex) : "f"(ax * ax * -1.4426950408889634f));
    const float er = fmaf(-p, ex, 1.0f);           // erf(|x|/sqrt(2))
    return fmaf(0.5f * axo, er, 0.5f * x);
}

// D += A(m16k16,row) * B(k16n8,col)  bf16 -> f32
__device__ __forceinline__ void mma16816(float* c, const u32* a, const u32* b) {
    asm volatile(
        "mma.sync.aligned.m16n8k16.row.col.f32.bf16.bf16.f32 "
        "{%0,%1,%2,%3}, {%4,%5,%6,%7}, {%8,%9}, {%0,%1,%2,%3};"
        : "+f"(c[0]), "+f"(c[1]), "+f"(c[2]), "+f"(c[3])
        : "r"(a[0]), "r"(a[1]), "r"(a[2]), "r"(a[3]), "r"(b[0]), "r"(b[1]));
}

// ---------------------------------------------------------------------------
// Node precompute: 256 thr = 2 nodes x {A,B} x 64 ch. 64 weight regs/thread.
// ---------------------------------------------------------------------------
__global__ __launch_bounds__(256) void node_pre_kernel(
    const float* __restrict__ x, const float* __restrict__ W1,
    const float* __restrict__ b1, const int* __restrict__ ei, int n_nodes)
{
    const int t = threadIdx.x;
    const int c   = t & 63;
    const int ab  = (t >> 6) & 1;
    const int grp = t >> 7;

    if (blockIdx.x == 0) {
        int ok = 1;
        for (int q = t; q < 1024; q += blockDim.x)
            if (ei[2 * q + 1] != 0) ok = 0;
        ok = __syncthreads_and(ok);
        if (t == 0) g_idx64 = ok;
    }

    const int kofs = ab ? 64 : 0;
    u64 w[32];
#pragma unroll
    for (int q = 0; q < 32; q++)
        w[q] = pk2(W1[(kofs + 2 * q) * CH + c], W1[(kofs + 2 * q + 1) * CH + c]);
    const float bias = ab ? b1[c] : 0.0f;
    float* dst = ab ? g_B : g_A;

    __shared__ __align__(16) float xs[2][CH];

    for (int n0 = blockIdx.x * 2; n0 < n_nodes; n0 += gridDim.x * 2) {
        const int node = n0 + grp;
        if (ab == 0 && node < n_nodes) xs[grp][c] = x[(size_t)node * CH + c];
        __syncthreads();
        if (node < n_nodes) {
            const ulonglong2* xp = (const ulonglong2*)xs[grp];
            u64 a0 = 0ull, a1 = 0ull;
#pragma unroll
            for (int q = 0; q < 16; q++) {
                ulonglong2 xv = xp[q];
                a0 = fma2(xv.x, w[2 * q],     a0);
                a1 = fma2(xv.y, w[2 * q + 1], a1);
            }
            dst[(size_t)node * CH + c] = hsum2(add2(a0, a1)) + bias;
        }
        __syncthreads();
    }
}

// ---------------------------------------------------------------------------
// Edge kernel: 4 independent warps/block, each owning 32-edge tiles.
// ---------------------------------------------------------------------------
__global__ void __launch_bounds__(128, 3) edge_mma_kernel(
    const void* __restrict__ ei_raw,
    const float* __restrict__ ea,
    const float* __restrict__ W1,
    const float* __restrict__ gamma, const float* __restrict__ beta,
    const float* __restrict__ W2, const float* __restrict__ b2,
    float* __restrict__ out, int n_edges, int n_wtiles)
{
    // Weight B-fragment pairs as u64 words: [4*kt+tq][n], row pad 72.
    __shared__ uint2 sW1H64[8][72],  sW1L64[8][72];
    __shared__ uint2 sW2H64[16][72], sW2L64[16][72];
    __shared__ float sgm[64], sbt[64], sb2v[64];

    const int tid = threadIdx.x;
    for (int idx = tid; idx < 64 * 8; idx += 128) {        // W1 edge part
        int n = idx >> 3, kg = idx & 7;
        int kt = kg >> 2, t4 = kg & 3;
        int plo = 8 * kt + t4, phi = plo + 4;
        __nv_bfloat16 ha, la, hb, lb;
        split1(W1[(size_t)(128 + 2 * plo) * CH + n], ha, la);
        split1(W1[(size_t)(128 + 2 * plo + 1) * CH + n], hb, lb);
        u32 Hlo = pkbf(ha, hb), Llo = pkbf(la, lb);
        split1(W1[(size_t)(128 + 2 * phi) * CH + n], ha, la);
        split1(W1[(size_t)(128 + 2 * phi + 1) * CH + n], hb, lb);
        u32 Hhi = pkbf(ha, hb), Lhi = pkbf(la, lb);
        sW1H64[kg][n] = make_uint2(Hlo, Hhi);
        sW1L64[kg][n] = make_uint2(Llo, Lhi);
    }
    for (int idx = tid; idx < 64 * 16; idx += 128) {       // W2
        int n = idx >> 4, kg = idx & 15;
        int kt = kg >> 2, t4 = kg & 3;
        int plo = 8 * kt + t4, phi = plo + 4;
        __nv_bfloat16 ha, la, hb, lb;
        split1(W2[(size_t)(2 * plo) * CH + n], ha, la);
        split1(W2[(size_t)(2 * plo + 1) * CH + n], hb, lb);
        u32 Hlo = pkbf(ha, hb), Llo = pkbf(la, lb);
        split1(W2[(size_t)(2 * phi) * CH + n], ha, la);
        split1(W2[(size_t)(2 * phi + 1) * CH + n], hb, lb);
        u32 Hhi = pkbf(ha, hb), Lhi = pkbf(la, lb);
        sW2H64[kg][n] = make_uint2(Hlo, Hhi);
        sW2L64[kg][n] = make_uint2(Llo, Lhi);
    }
    if (tid < 64) { sgm[tid] = gamma[tid]; sbt[tid] = beta[tid]; sb2v[tid] = b2[tid]; }
    __syncthreads();

    const int wid = tid >> 5, lane = tid & 31;
    const int q = lane >> 2, tq = lane & 3;
    const int flag64 = g_idx64;
    const long long* ei64 = (const long long*)ei_raw;
    const int*       ei32 = (const int*)ei_raw;
    const int wstep = gridDim.x * 4;

    auto ldidx = [&](int wtt, int* I, int* J) {
#pragma unroll
        for (int r4 = 0; r4 < 4; r4++) {
            int row = ((r4 >> 1) << 4) + ((r4 & 1) << 3) + q;
            long long e = (long long)wtt * 32 + row;
            if (wtt >= n_wtiles || e >= n_edges) e = 0;
            if (flag64) { I[r4] = (int)ei64[e]; J[r4] = (int)ei64[(size_t)n_edges + e]; }
            else        { I[r4] = ei32[e];      J[r4] = ei32[(size_t)n_edges + e]; }
        }
    };

    int wt = blockIdx.x * 4 + wid;
    int iv[4], jv[4];
    ldidx(wt, iv, jv);

    for (; wt < n_wtiles; wt += wstep) {
        const int eb = wt * 32;

        // ---- acc1 init = s = A[i]+B[j] (fragment-layout gather) ----------
        float acc[2][8][4];
#pragma unroll
        for (int mt = 0; mt < 2; mt++) {
            const float2* pa0 = (const float2*)(g_A + (size_t)iv[2 * mt]     * CH);
            const float2* pb0 = (const float2*)(g_B + (size_t)jv[2 * mt]     * CH);
            const float2* pa8 = (const float2*)(g_A + (size_t)iv[2 * mt + 1] * CH);
            const float2* pb8 = (const float2*)(g_B + (size_t)jv[2 * mt + 1] * CH);
#pragma unroll
            for (int nt = 0; nt < 8; nt++) {
                float2 x0 = pa0[4 * nt + tq], y0 = pb0[4 * nt + tq];
                float2 x8 = pa8[4 * nt + tq], y8 = pb8[4 * nt + tq];
                acc[mt][nt][0] = x0.x + y0.x;  acc[mt][nt][1] = x0.y + y0.y;
                acc[mt][nt][2] = x8.x + y8.x;  acc[mt][nt][3] = x8.y + y8.y;
            }
        }

        // ---- ea A-fragments (fast hi/lo split) ---------------------------
        u32 eH[2][2][4], eL[2][2][4];
#pragma unroll
        for (int mt = 0; mt < 2; mt++)
#pragma unroll
            for (int g8 = 0; g8 < 2; g8++) {
                int row = mt * 16 + g8 * 8 + q;
                int e = eb + row; if (e >= n_edges) e = 0;
                const float2* pe = (const float2*)(ea + (size_t)e * ED);
#pragma unroll
                for (int kt = 0; kt < 2; kt++)
#pragma unroll
                    for (int gr = 0; gr < 2; gr++) {
                        float2 v = pe[8 * kt + 4 * gr + tq];
                        eH[mt][kt][gr * 2 + g8] = hi_pair(v.x, v.y);
                        eL[mt][kt][gr * 2 + g8] = lo_pair(v.x, v.y);
                    }
            }

        // ---- prefetch next tile's indices (covers idx->gather latency) ---
        int ivn[4], jvn[4];
        ldidx(wt + wstep, ivn, jvn);

        // ---- GEMM1: acc += ea @ W1e (3-term split) -----------------------
#pragma unroll
        for (int kt = 0; kt < 2; kt++)
#pragma unroll
            for (int nt = 0; nt < 8; nt++) {
                int nr = 8 * nt + q;
                uint2 BH = sW1H64[4 * kt + tq][nr];
                uint2 BL = sW1L64[4 * kt + tq][nr];
                u32 bH[2] = { BH.x, BH.y };
                u32 bL[2] = { BL.x, BL.y };
#pragma unroll
                for (int mt = 0; mt < 2; mt++) {
                    mma16816(acc[mt][nt], eH[mt][kt], bH);
                    mma16816(acc[mt][nt], eH[mt][kt], bL);
                    mma16816(acc[mt][nt], eL[mt][kt], bH);
                }
            }

        // ---- LayerNorm stats: quad reduce (2 shfl) per row ---------------
        float mean[2][2], rstd[2][2];
#pragma unroll
        for (int mt = 0; mt < 2; mt++)
#pragma unroll
            for (int g8 = 0; g8 < 2; g8++) {
                u64 ssp = 0ull;
#pragma unroll
                for (int nt = 0; nt < 8; nt++) {
                    float v0 = acc[mt][nt][2 * g8], v1 = acc[mt][nt][2 * g8 + 1];
                    ssp = add2(ssp, pk2(v0 + v1, fmaf(v0, v0, v1 * v1)));
                }
                ssp = add2(ssp, __shfl_xor_sync(0xffffffffu, ssp, 1));
                ssp = add2(ssp, __shfl_xor_sync(0xffffffffu, ssp, 2));
                float s, s2; unpk2(ssp, s, s2);
                float mu = s * (1.0f / 64.0f);
                mean[mt][g8] = mu;
                rstd[mt][g8] = rsqrtf(s2 * (1.0f / 64.0f) - mu * mu + 1e-5f);
            }

        // ---- LN + fast GELU + fast split -> GEMM2 A-fragments ------------
        u32 gh[2][2][8], gl[2][2][8];
#pragma unroll
        for (int mt = 0; mt < 2; mt++)
#pragma unroll
            for (int nt = 0; nt < 8; nt++) {
                float2 gm = *(const float2*)&sgm[8 * nt + 2 * tq];
                float2 bt = *(const float2*)&sbt[8 * nt + 2 * tq];
#pragma unroll
                for (int g8 = 0; g8 < 2; g8++) {
                    float h0 = fmaf((acc[mt][nt][2 * g8]     - mean[mt][g8]) * rstd[mt][g8], gm.x, bt.x);
                    float h1 = fmaf((acc[mt][nt][2 * g8 + 1] - mean[mt][g8]) * rstd[mt][g8], gm.y, bt.y);
                    float e0 = gelu_fast(h0);
                    float e1 = gelu_fast(h1);
                    gh[mt][g8][nt] = hi_pair(e0, e1);
                    gl[mt][g8][nt] = lo_pair(e0, e1);
                }
            }

        // ---- GEMM2 + scatter in two sequential N-halves ------------------
#pragma unroll 1
        for (int half = 0; half < 2; half++) {
            float acc2[2][4][4];
#pragma unroll
            for (int mt = 0; mt < 2; mt++)
#pragma unroll
                for (int n4 = 0; n4 < 4; n4++) {
                    int nt = half * 4 + n4;
                    float2 b2p = *(const float2*)&sb2v[8 * nt + 2 * tq];
                    acc2[mt][n4][0] = b2p.x; acc2[mt][n4][1] = b2p.y;
                    acc2[mt][n4][2] = b2p.x; acc2[mt][n4][3] = b2p.y;
                }
#pragma unroll
            for (int kt = 0; kt < 4; kt++)
#pragma unroll
                for (int n4 = 0; n4 < 4; n4++) {
                    int nt = half * 4 + n4;
                    int nr = 8 * nt + q;
                    uint2 BH = sW2H64[4 * kt + tq][nr];
                    uint2 BL = sW2L64[4 * kt + tq][nr];
                    u32 bH[2] = { BH.x, BH.y };
                    u32 bL[2] = { BL.x, BL.y };
#pragma unroll
                    for (int mt = 0; mt < 2; mt++) {
                        u32 aH[4] = { gh[mt][0][2 * kt], gh[mt][1][2 * kt],
                                      gh[mt][0][2 * kt + 1], gh[mt][1][2 * kt + 1] };
                        u32 aL[4] = { gl[mt][0][2 * kt], gl[mt][1][2 * kt],
                                      gl[mt][0][2 * kt + 1], gl[mt][1][2 * kt + 1] };
                        mma16816(acc2[mt][n4], aH, bH);
                        mma16816(acc2[mt][n4], aH, bL);
                        mma16816(acc2[mt][n4], aL, bH);
                    }
                }
#pragma unroll
            for (int mt = 0; mt < 2; mt++)
#pragma unroll
                for (int g8 = 0; g8 < 2; g8++) {
                    int row = mt * 16 + g8 * 8 + q;
                    int e = eb + row;
                    if (e < n_edges) {
                        float* op = out + (size_t)jv[2 * mt + g8] * CH + 2 * tq;
#pragma unroll
                        for (int n4 = 0; n4 < 4; n4++)
                            red2(op + 8 * (half * 4 + n4),
                                 acc2[mt][n4][2 * g8], acc2[mt][n4][2 * g8 + 1]);
                    }
                }
        }

        // ---- rotate prefetched indices -----------------------------------
#pragma unroll
        for (int r4 = 0; r4 < 4; r4++) { iv[r4] = ivn[r4]; jv[r4] = jvn[r4]; }
    }
}

// ---------------------------------------------------------------------------
// Inputs: x[N,64] f32, edge_index[2,E] (i32/i64), edge_attr[E,32] f32,
// W1[160,64], b1[64], gamma[64], beta[64], W2[64,64], b2[64]. Out [N,64] f32.
// ---------------------------------------------------------------------------
extern "C" void kernel_launch(void* const* d_in, const int* in_sizes, int n_in,
                              void* d_out, int out_size)
{
    const float* x     = (const float*)d_in[0];
    const void*  ei    = d_in[1];
    const float* ea    = (const float*)d_in[2];
    const float* W1    = (const float*)d_in[3];
    const float* b1    = (const float*)d_in[4];
    const float* gamma = (const float*)d_in[5];
    const float* beta  = (const float*)d_in[6];
    const float* W2    = (const float*)d_in[7];
    const float* b2    = (const float*)d_in[8];
    float* out = (float*)d_out;

    const int n_nodes  = in_sizes[0] / CH;
    const int n_edges  = in_sizes[2] / ED;
    const int n_wtiles = (n_edges + 31) / 32;
    if (n_nodes > MAXN) return;

    cudaMemsetAsync(d_out, 0, (size_t)out_size * sizeof(float));

    node_pre_kernel<<<592, 256>>>(x, W1, b1, (const int*)ei, n_nodes);

    edge_mma_kernel<<<444, 128>>>(ei, ea, W1, gamma, beta, W2, b2,
                                  out, n_edges, n_wtiles);
}